// round 2
// baseline (speedup 1.0000x reference)
#include <cuda_runtime.h>
#include <math.h>

// ---------------- dimensions ----------------
#define BB   2
#define TT   1024
#define CC   768
#define NH   12
#define HD   64
#define LL   4
#define VV   50257
#define NTOK 2048          // BB*TT
#define BH   24            // BB*NH

// ---------------- scratch (static device globals; no allocs) ----------------
__device__ float g_x  [NTOK * CC];
__device__ float g_h  [NTOK * CC];
__device__ float g_qkv[NTOK * 3 * CC];
__device__ float g_y  [NTOK * CC];
__device__ float g_m1 [NTOK * 4 * CC];

// ---------------- reduction helpers ----------------
__device__ __forceinline__ float warpReduceSum(float v) {
    #pragma unroll
    for (int o = 16; o > 0; o >>= 1) v += __shfl_xor_sync(0xffffffffu, v, o);
    return v;
}
__device__ float blockReduceSum(float v) {
    __shared__ float s[32];
    int lane = threadIdx.x & 31, wid = threadIdx.x >> 5;
    v = warpReduceSum(v);
    if (lane == 0) s[wid] = v;
    __syncthreads();
    int nw = blockDim.x >> 5;
    v = (threadIdx.x < nw) ? s[threadIdx.x] : 0.f;
    if (wid == 0) v = warpReduceSum(v);
    if (threadIdx.x == 0) s[0] = v;
    __syncthreads();
    v = s[0];
    __syncthreads();
    return v;
}

__device__ __forceinline__ float gelu_f(float x) {
    const float k = 0.7978845608028654f;  // sqrt(2/pi)
    float x3 = x * x * x;
    return 0.5f * x * (1.f + tanhf(k * (x + 0.044715f * x3)));
}

// ---------------- embedding ----------------
__global__ void embed_k(const int* __restrict__ idx, const float* __restrict__ wte,
                        const float* __restrict__ wpe, float* __restrict__ x) {
    int row = blockIdx.x;              // b*TT + t
    int t = row & (TT - 1);
    int tok = idx[row];
    const float* we = wte + (size_t)tok * CC;
    const float* pe = wpe + (size_t)t * CC;
    float* o = x + (size_t)row * CC;
    for (int c = threadIdx.x; c < CC; c += blockDim.x) o[c] = we[c] + pe[c];
}

// ---------------- layernorm (block per row, 256 threads, 3 elems/thread) ----------------
__global__ void layernorm_k(const float* __restrict__ in, const float* __restrict__ w,
                            const float* __restrict__ b, float* __restrict__ out) {
    int row = blockIdx.x;
    const float* p = in + (size_t)row * CC;
    int tid = threadIdx.x;
    float v[3];
    float s = 0.f;
    #pragma unroll
    for (int i = 0; i < 3; i++) { v[i] = p[tid + i * 256]; s += v[i]; }
    float mean = blockReduceSum(s) * (1.f / (float)CC);
    float vs = 0.f;
    #pragma unroll
    for (int i = 0; i < 3; i++) { float d = v[i] - mean; vs += d * d; }
    float var = blockReduceSum(vs) * (1.f / (float)CC);
    float rstd = rsqrtf(var + 1e-5f);
    float* o = out + (size_t)row * CC;
    #pragma unroll
    for (int i = 0; i < 3; i++) {
        int c = tid + i * 256;
        o[c] = (v[i] - mean) * rstd * w[c] + b[c];
    }
}

// ---------------- generic SGEMM: C = epi(A[MxK] @ B[KxN]) ----------------
// 128x128 tile, BK=8, 256 threads, 8x8 per thread.
template <bool BIAS, bool GELU, bool RESID>
__global__ __launch_bounds__(256) void sgemm_k(
    const float* __restrict__ A, const float* __restrict__ B,
    const float* __restrict__ bias, const float* __restrict__ resid,
    float* __restrict__ C, int M, int N, int K) {
    __shared__ float As[8][128];
    __shared__ float Bs[8][128];
    int tid = threadIdx.x;
    int row0 = blockIdx.y * 128;
    int col0 = blockIdx.x * 128;

    int aRow = tid >> 1;            // 0..127
    int aCol = (tid & 1) * 4;       // 0 or 4
    int bRow = tid >> 5;            // 0..7
    int bCol = tid & 31;            // cols bCol + 32u

    int trow = (tid >> 4) * 8;
    int tcol = (tid & 15) * 8;

    float acc[8][8];
    #pragma unroll
    for (int i = 0; i < 8; i++)
        #pragma unroll
        for (int j = 0; j < 8; j++) acc[i][j] = 0.f;

    const float* Aptr = A + (size_t)(row0 + aRow) * K + aCol;
    bool fullN = (col0 + 128 <= N);

    for (int kt = 0; kt < K; kt += 8) {
        float4 a4 = *(const float4*)(Aptr + kt);
        As[aCol + 0][aRow] = a4.x;
        As[aCol + 1][aRow] = a4.y;
        As[aCol + 2][aRow] = a4.z;
        As[aCol + 3][aRow] = a4.w;
        const float* Bp = B + (size_t)(kt + bRow) * N + col0;
        if (fullN) {
            #pragma unroll
            for (int u = 0; u < 4; u++) {
                int c = bCol + u * 32;
                Bs[bRow][c] = Bp[c];
            }
        } else {
            #pragma unroll
            for (int u = 0; u < 4; u++) {
                int c = bCol + u * 32;
                Bs[bRow][c] = (col0 + c < N) ? Bp[c] : 0.f;
            }
        }
        __syncthreads();
        #pragma unroll
        for (int k = 0; k < 8; k++) {
            float4 a0 = *(float4*)&As[k][trow];
            float4 a1 = *(float4*)&As[k][trow + 4];
            float4 b0 = *(float4*)&Bs[k][tcol];
            float4 b1 = *(float4*)&Bs[k][tcol + 4];
            float av[8] = {a0.x, a0.y, a0.z, a0.w, a1.x, a1.y, a1.z, a1.w};
            float bv[8] = {b0.x, b0.y, b0.z, b0.w, b1.x, b1.y, b1.z, b1.w};
            #pragma unroll
            for (int i = 0; i < 8; i++)
                #pragma unroll
                for (int j = 0; j < 8; j++) acc[i][j] += av[i] * bv[j];
        }
        __syncthreads();
    }

    #pragma unroll
    for (int i = 0; i < 8; i++) {
        int r = row0 + trow + i;
        #pragma unroll
        for (int j = 0; j < 8; j++) {
            int c = col0 + tcol + j;
            if (c < N) {
                float v = acc[i][j];
                if (BIAS) v += bias[c];
                if (GELU) v = gelu_f(v);
                if (RESID) v += resid[(size_t)r * N + c];
                C[(size_t)r * N + c] = v;
            }
        }
    }
}

// ---------------- fused flash attention ----------------
// grid (TT/64, BH), block 256. 64 query rows per block, online softmax over
// causal s-tiles of 64. Q and K stored transposed ([d][row]) for conflict-free
// float4 smem reads in the S loop; P written transposed ([s][t]) into the K
// buffer for conflict-free float4 reads in the PV loop.
__global__ __launch_bounds__(256) void flash_attn_k(const float* __restrict__ qkv,
                                                    float* __restrict__ y) {
    __shared__ float Qt [64][64];   // [d][t]
    __shared__ float KPt[64][64];   // phase 1: K^T [d][s]; phase 2: P^T [s][t]
    __shared__ float Vs [64][64];   // [s][d]

    int bh = blockIdx.y;
    int b = bh / NH, h = bh % NH;
    int t0 = blockIdx.x * 64;
    int tid = threadIdx.x;
    int ty = tid >> 4, tx = tid & 15;

    // load Q tile transposed (once)
    #pragma unroll
    for (int u = 0; u < 4; u++) {
        int idx = tid + u * 256;
        int r = idx >> 4;
        int c4 = (idx & 15) * 4;
        const float* qsrc = qkv + (size_t)(b * TT + t0 + r) * (3 * CC) + h * HD + c4;
        float4 qv = *(const float4*)qsrc;
        Qt[c4 + 0][r] = qv.x;
        Qt[c4 + 1][r] = qv.y;
        Qt[c4 + 2][r] = qv.z;
        Qt[c4 + 3][r] = qv.w;
    }

    float m_i[4], l_i[4], acc[4][4];
    #pragma unroll
    for (int i = 0; i < 4; i++) {
        m_i[i] = -1e30f;
        l_i[i] = 0.f;
        #pragma unroll
        for (int j = 0; j < 4; j++) acc[i][j] = 0.f;
    }

    int nTiles = blockIdx.x + 1;          // causal: s-tiles 0..blockIdx.x
    for (int st = 0; st < nTiles; st++) {
        int s0 = st * 64;

        __syncthreads();  // previous PV / Qt writes complete before refill
        #pragma unroll
        for (int u = 0; u < 4; u++) {
            int idx = tid + u * 256;
            int r = idx >> 4;
            int c4 = (idx & 15) * 4;
            const float* ksrc = qkv + (size_t)(b * TT + s0 + r) * (3 * CC) + CC + h * HD + c4;
            float4 kv = *(const float4*)ksrc;
            KPt[c4 + 0][r] = kv.x;
            KPt[c4 + 1][r] = kv.y;
            KPt[c4 + 2][r] = kv.z;
            KPt[c4 + 3][r] = kv.w;
            const float* vsrc = qkv + (size_t)(b * TT + s0 + r) * (3 * CC) + 2 * CC + h * HD + c4;
            *(float4*)&Vs[r][c4] = *(const float4*)vsrc;
        }
        __syncthreads();

        // S[i][j] = sum_d Q[t][d] * K[s][d],  t = t0+ty*4+i,  s = s0+tx*4+j
        float S[4][4];
        #pragma unroll
        for (int i = 0; i < 4; i++)
            #pragma unroll
            for (int j = 0; j < 4; j++) S[i][j] = 0.f;

        #pragma unroll 8
        for (int d = 0; d < 64; d++) {
            float4 aq = *(float4*)&Qt[d][ty * 4];
            float4 bq = *(float4*)&KPt[d][tx * 4];
            float av[4] = {aq.x, aq.y, aq.z, aq.w};
            float bv[4] = {bq.x, bq.y, bq.z, bq.w};
            #pragma unroll
            for (int i = 0; i < 4; i++)
                #pragma unroll
                for (int j = 0; j < 4; j++) S[i][j] += av[i] * bv[j];
        }

        __syncthreads();  // all K reads done; KPt becomes P^T below

        const float scale = 0.125f;  // 1/sqrt(64)
        bool diag = (st == blockIdx.x);
        #pragma unroll
        for (int i = 0; i < 4; i++) {
            int t = t0 + ty * 4 + i;
            #pragma unroll
            for (int j = 0; j < 4; j++) {
                float v = S[i][j] * scale;
                if (diag && (s0 + tx * 4 + j > t)) v = -1e30f;
                S[i][j] = v;
            }
        }

        // online softmax update (row groups of 16 lanes sharing same ty)
        #pragma unroll
        for (int i = 0; i < 4; i++) {
            float rmax = fmaxf(fmaxf(S[i][0], S[i][1]), fmaxf(S[i][2], S[i][3]));
            #pragma unroll
            for (int o = 8; o > 0; o >>= 1)
                rmax = fmaxf(rmax, __shfl_xor_sync(0xffffffffu, rmax, o));
            float mnew = fmaxf(m_i[i], rmax);
            float alpha = __expf(m_i[i] - mnew);
            float rsum = 0.f;
            #pragma unroll
            for (int j = 0; j < 4; j++) {
                float p = __expf(S[i][j] - mnew);
                S[i][j] = p;
                rsum += p;
            }
            #pragma unroll
            for (int o = 8; o > 0; o >>= 1)
                rsum += __shfl_xor_sync(0xffffffffu, rsum, o);
            l_i[i] = l_i[i] * alpha + rsum;
            m_i[i] = mnew;
            #pragma unroll
            for (int j = 0; j < 4; j++) acc[i][j] *= alpha;
        }

        // write P transposed: KPt[s][t]
        #pragma unroll
        for (int i = 0; i < 4; i++)
            #pragma unroll
            for (int j = 0; j < 4; j++)
                KPt[tx * 4 + j][ty * 4 + i] = S[i][j];
        __syncthreads();

        // acc += P @ V  (thread covers rows ty*4+i, d-cols tx*4+j)
        #pragma unroll 8
        for (int k = 0; k < 64; k++) {
            float4 ap = *(float4*)&KPt[k][ty * 4];
            float4 vv = *(float4*)&Vs[k][tx * 4];
            float av[4] = {ap.x, ap.y, ap.z, ap.w};
            float bv[4] = {vv.x, vv.y, vv.z, vv.w};
            #pragma unroll
            for (int i = 0; i < 4; i++)
                #pragma unroll
                for (int j = 0; j < 4; j++) acc[i][j] += av[i] * bv[j];
        }
    }

    #pragma unroll
    for (int i = 0; i < 4; i++) {
        float inv = 1.f / l_i[i];
        int t = t0 + ty * 4 + i;
        float* orow = y + (size_t)(b * TT + t) * CC + h * HD;
        #pragma unroll
        for (int j = 0; j < 4; j++) orow[tx * 4 + j] = acc[i][j] * inv;
    }
}

// ---------------- host launcher ----------------
extern "C" void kernel_launch(void* const* d_in, const int* in_sizes, int n_in,
                              void* d_out, int out_size) {
    (void)in_sizes; (void)n_in; (void)out_size;
    const int*   idx    = (const int*)  d_in[0];
    const float* wte    = (const float*)d_in[1];
    const float* wpe    = (const float*)d_in[2];
    const float* ln1_w  = (const float*)d_in[3];
    const float* ln1_b  = (const float*)d_in[4];
    const float* qkv_w  = (const float*)d_in[5];
    const float* qkv_b  = (const float*)d_in[6];
    const float* proj_w = (const float*)d_in[7];
    const float* proj_b = (const float*)d_in[8];
    const float* ln2_w  = (const float*)d_in[9];
    const float* ln2_b  = (const float*)d_in[10];
    const float* fc_w   = (const float*)d_in[11];
    const float* fc_b   = (const float*)d_in[12];
    const float* fc2_w  = (const float*)d_in[13];
    const float* fc2_b  = (const float*)d_in[14];
    const float* lnf_w  = (const float*)d_in[15];
    const float* lnf_b  = (const float*)d_in[16];
    const float* head_w = (const float*)d_in[17];
    float* out = (float*)d_out;

    float *x, *h, *qkv, *y, *m1;
    cudaGetSymbolAddress((void**)&x,   g_x);
    cudaGetSymbolAddress((void**)&h,   g_h);
    cudaGetSymbolAddress((void**)&qkv, g_qkv);
    cudaGetSymbolAddress((void**)&y,   g_y);
    cudaGetSymbolAddress((void**)&m1,  g_m1);

    embed_k<<<NTOK, 256>>>(idx, wte, wpe, x);

    for (int l = 0; l < LL; l++) {
        const float* l_ln1w  = ln1_w  + (size_t)l * CC;
        const float* l_ln1b  = ln1_b  + (size_t)l * CC;
        const float* l_qkvw  = qkv_w  + (size_t)l * CC * 3 * CC;
        const float* l_qkvb  = qkv_b  + (size_t)l * 3 * CC;
        const float* l_pw    = proj_w + (size_t)l * CC * CC;
        const float* l_pb    = proj_b + (size_t)l * CC;
        const float* l_ln2w  = ln2_w  + (size_t)l * CC;
        const float* l_ln2b  = ln2_b  + (size_t)l * CC;
        const float* l_fcw   = fc_w   + (size_t)l * CC * 4 * CC;
        const float* l_fcb   = fc_b   + (size_t)l * 4 * CC;
        const float* l_fc2w  = fc2_w  + (size_t)l * 4 * CC * CC;
        const float* l_fc2b  = fc2_b  + (size_t)l * CC;

        layernorm_k<<<NTOK, 256>>>(x, l_ln1w, l_ln1b, h);
        sgemm_k<true, false, false><<<dim3((3 * CC) / 128, NTOK / 128), 256>>>(
            h, l_qkvw, l_qkvb, nullptr, qkv, NTOK, 3 * CC, CC);
        flash_attn_k<<<dim3(TT / 64, BH), 256>>>(qkv, y);
        sgemm_k<true, false, true><<<dim3(CC / 128, NTOK / 128), 256>>>(
            y, l_pw, l_pb, x, x, NTOK, CC, CC);
        layernorm_k<<<NTOK, 256>>>(x, l_ln2w, l_ln2b, h);
        sgemm_k<true, true, false><<<dim3((4 * CC) / 128, NTOK / 128), 256>>>(
            h, l_fcw, l_fcb, nullptr, m1, NTOK, 4 * CC, CC);
        sgemm_k<true, false, true><<<dim3(CC / 128, NTOK / 128), 256>>>(
            m1, l_fc2w, l_fc2b, x, x, NTOK, CC, 4 * CC);
    }

    layernorm_k<<<NTOK, 256>>>(x, lnf_w, lnf_b, h);
    sgemm_k<false, false, false><<<dim3((VV + 127) / 128, NTOK / 128), 256>>>(
        h, head_w, nullptr, nullptr, out, NTOK, VV, CC);
}

// round 4
// speedup vs baseline: 1.7856x; 1.7856x over previous
#include <cuda_runtime.h>
#include <math.h>
#include <stdint.h>

// ---------------- dimensions ----------------
#define BB   2
#define TT   1024
#define CC   768
#define NH   12
#define HD   64
#define LL   4
#define VV   50257
#define NTOK 2048          // BB*TT
#define BH   24            // BB*NH

// ---------------- scratch (static device globals; no allocs) ----------------
__device__ float g_x  [NTOK * CC];
__device__ float g_h  [NTOK * CC];
__device__ float g_qkv[NTOK * 3 * CC];
__device__ float g_y  [NTOK * CC];
__device__ float g_m1 [NTOK * 4 * CC];

// ---------------- reduction helpers ----------------
__device__ __forceinline__ float warpReduceSum(float v) {
    #pragma unroll
    for (int o = 16; o > 0; o >>= 1) v += __shfl_xor_sync(0xffffffffu, v, o);
    return v;
}
__device__ float blockReduceSum(float v) {
    __shared__ float s[32];
    int lane = threadIdx.x & 31, wid = threadIdx.x >> 5;
    v = warpReduceSum(v);
    if (lane == 0) s[wid] = v;
    __syncthreads();
    int nw = blockDim.x >> 5;
    v = (threadIdx.x < nw) ? s[threadIdx.x] : 0.f;
    if (wid == 0) v = warpReduceSum(v);
    if (threadIdx.x == 0) s[0] = v;
    __syncthreads();
    v = s[0];
    __syncthreads();
    return v;
}

__device__ __forceinline__ float gelu_f(float x) {
    const float k = 0.7978845608028654f;  // sqrt(2/pi)
    float x3 = x * x * x;
    return 0.5f * x * (1.f + tanhf(k * (x + 0.044715f * x3)));
}

__device__ __forceinline__ uint32_t f2tf32(float x) {
    uint32_t r;
    asm("cvt.rna.tf32.f32 %0, %1;" : "=r"(r) : "f"(x));
    return r;
}

__device__ __forceinline__ void mma_tf32(float c[4],
                                         uint32_t a0, uint32_t a1, uint32_t a2, uint32_t a3,
                                         uint32_t b0, uint32_t b1) {
    asm volatile(
        "mma.sync.aligned.m16n8k8.row.col.f32.tf32.tf32.f32 "
        "{%0,%1,%2,%3}, {%4,%5,%6,%7}, {%8,%9}, {%0,%1,%2,%3};\n"
        : "+f"(c[0]), "+f"(c[1]), "+f"(c[2]), "+f"(c[3])
        : "r"(a0), "r"(a1), "r"(a2), "r"(a3), "r"(b0), "r"(b1));
}

// ---------------- embedding ----------------
__global__ void embed_k(const int* __restrict__ idx, const float* __restrict__ wte,
                        const float* __restrict__ wpe, float* __restrict__ x) {
    int row = blockIdx.x;              // b*TT + t
    int t = row & (TT - 1);
    int tok = idx[row];
    const float* we = wte + (size_t)tok * CC;
    const float* pe = wpe + (size_t)t * CC;
    float* o = x + (size_t)row * CC;
    for (int c = threadIdx.x; c < CC; c += blockDim.x) o[c] = we[c] + pe[c];
}

// ---------------- layernorm (block per row, 256 threads, 3 elems/thread) ----------------
__global__ void layernorm_k(const float* __restrict__ in, const float* __restrict__ w,
                            const float* __restrict__ b, float* __restrict__ out) {
    int row = blockIdx.x;
    const float* p = in + (size_t)row * CC;
    int tid = threadIdx.x;
    float v[3];
    float s = 0.f;
    #pragma unroll
    for (int i = 0; i < 3; i++) { v[i] = p[tid + i * 256]; s += v[i]; }
    float mean = blockReduceSum(s) * (1.f / (float)CC);
    float vs = 0.f;
    #pragma unroll
    for (int i = 0; i < 3; i++) { float d = v[i] - mean; vs += d * d; }
    float var = blockReduceSum(vs) * (1.f / (float)CC);
    float rstd = rsqrtf(var + 1e-5f);
    float* o = out + (size_t)row * CC;
    #pragma unroll
    for (int i = 0; i < 3; i++) {
        int c = tid + i * 256;
        o[c] = (v[i] - mean) * rstd * w[c] + b[c];
    }
}

// ---------------- TF32 tensor-core GEMM: C = epi(A[MxK] @ B[KxN]) ----------------
// 128x128 block tile, KT=32, 256 threads = 8 warps.
// Warp grid 2(m) x 4(n); each warp: 64x32 via 4x4 m16n8k8 MMAs.
// Smem holds tf32-converted operands, stride 132 (pad 4) for conflict-free frag loads.
// B loads are vectorized only when the B row stride N is a multiple of 4
// (the LM head has N=50257, odd -> scalar path; float4 there traps on alignment).
#define KT 32
#define SST 132
template <bool BIAS, bool GELU, bool RESID>
__global__ __launch_bounds__(256) void tgemm_k(
    const float* __restrict__ A, const float* __restrict__ B,
    const float* __restrict__ bias, const float* __restrict__ resid,
    float* __restrict__ C, int M, int N, int K) {
    __shared__ uint32_t As[KT][SST];   // [k][m] (A transposed)
    __shared__ uint32_t Bs[KT][SST];   // [k][n]

    int tid = threadIdx.x;
    int lane = tid & 31;
    int wid = tid >> 5;
    int warp_m = wid >> 2;             // 0..1
    int warp_n = wid & 3;              // 0..3
    int lr = lane >> 2;                // 0..7
    int lc = lane & 3;                 // 0..3

    int row0 = blockIdx.y * 128;
    int col0 = blockIdx.x * 128;

    // A gmem load mapping: 4 rows per thread, 1 float4 each
    int aM = tid >> 3;                 // 0..31, +u*32
    int aK = (tid & 7) * 4;            // 0..28
    // B gmem load mapping: 1 row, 4 float4 at stride 32
    int bK = tid >> 3;                 // 0..31
    int bN = (tid & 7) * 4;            // +u*32

    bool fullN = (col0 + 128 <= N);
    bool vecB = fullN && ((N & 3) == 0);

    float acc[4][4][4];
    #pragma unroll
    for (int i = 0; i < 4; i++)
        #pragma unroll
        for (int j = 0; j < 4; j++)
            #pragma unroll
            for (int q = 0; q < 4; q++) acc[i][j][q] = 0.f;

    for (int kt = 0; kt < K; kt += KT) {
        // ---- load A tile (transpose into As[k][m], cvt to tf32) ----
        #pragma unroll
        for (int u = 0; u < 4; u++) {
            int m = aM + u * 32;
            const float* src = A + (size_t)(row0 + m) * K + kt + aK;
            float4 v = *(const float4*)src;
            As[aK + 0][m] = f2tf32(v.x);
            As[aK + 1][m] = f2tf32(v.y);
            As[aK + 2][m] = f2tf32(v.z);
            As[aK + 3][m] = f2tf32(v.w);
        }
        // ---- load B tile (Bs[k][n], cvt to tf32) ----
        if (vecB) {
            const float* src = B + (size_t)(kt + bK) * N + col0 + bN;
            #pragma unroll
            for (int u = 0; u < 4; u++) {
                float4 v = *(const float4*)(src + u * 32);
                uint4 w;
                w.x = f2tf32(v.x); w.y = f2tf32(v.y);
                w.z = f2tf32(v.z); w.w = f2tf32(v.w);
                *(uint4*)&Bs[bK][bN + u * 32] = w;
            }
        } else if (fullN) {
            const float* src = B + (size_t)(kt + bK) * N + col0;
            #pragma unroll
            for (int u = 0; u < 4; u++) {
                #pragma unroll
                for (int q = 0; q < 4; q++) {
                    int c = bN + u * 32 + q;
                    Bs[bK][c] = f2tf32(src[c]);
                }
            }
        } else {
            const float* src = B + (size_t)(kt + bK) * N;
            #pragma unroll
            for (int u = 0; u < 4; u++) {
                #pragma unroll
                for (int q = 0; q < 4; q++) {
                    int c = bN + u * 32 + q;
                    float v = (col0 + c < N) ? src[col0 + c] : 0.f;
                    Bs[bK][c] = f2tf32(v);
                }
            }
        }
        __syncthreads();

        // ---- 4 k-steps of 8 ----
        #pragma unroll
        for (int ks = 0; ks < 4; ks++) {
            int k0 = ks * 8;
            uint32_t af[4][4];
            #pragma unroll
            for (int mt = 0; mt < 4; mt++) {
                int am = warp_m * 64 + mt * 16;
                af[mt][0] = As[k0 + lc    ][am + lr    ];
                af[mt][1] = As[k0 + lc    ][am + lr + 8];
                af[mt][2] = As[k0 + lc + 4][am + lr    ];
                af[mt][3] = As[k0 + lc + 4][am + lr + 8];
            }
            #pragma unroll
            for (int nt = 0; nt < 4; nt++) {
                int bn = warp_n * 32 + nt * 8;
                uint32_t b0 = Bs[k0 + lc    ][bn + lr];
                uint32_t b1 = Bs[k0 + 4 + lc][bn + lr];
                #pragma unroll
                for (int mt = 0; mt < 4; mt++)
                    mma_tf32(acc[mt][nt], af[mt][0], af[mt][1], af[mt][2], af[mt][3], b0, b1);
            }
        }
        __syncthreads();
    }

    // ---- epilogue ----
    #pragma unroll
    for (int mt = 0; mt < 4; mt++) {
        int rbase = row0 + warp_m * 64 + mt * 16 + lr;
        #pragma unroll
        for (int nt = 0; nt < 4; nt++) {
            int cbase = col0 + warp_n * 32 + nt * 8 + lc * 2;
            #pragma unroll
            for (int half = 0; half < 2; half++) {
                int r = rbase + half * 8;
                #pragma unroll
                for (int q = 0; q < 2; q++) {
                    int c = cbase + q;
                    if (c < N) {
                        float v = acc[mt][nt][half * 2 + q];
                        if (BIAS) v += bias[c];
                        if (GELU) v = gelu_f(v);
                        if (RESID) v += resid[(size_t)r * N + c];
                        C[(size_t)r * N + c] = v;
                    }
                }
            }
        }
    }
}

// ---------------- fused flash attention (fp32) ----------------
// grid (TT/64, BH), block 256. 64 query rows per block, online softmax over
// causal s-tiles of 64.
__global__ __launch_bounds__(256) void flash_attn_k(const float* __restrict__ qkv,
                                                    float* __restrict__ y) {
    __shared__ float Qt [64][64];   // [d][t]
    __shared__ float KPt[64][64];   // phase 1: K^T [d][s]; phase 2: P^T [s][t]
    __shared__ float Vs [64][64];   // [s][d]

    int bh = blockIdx.y;
    int b = bh / NH, h = bh % NH;
    int t0 = blockIdx.x * 64;
    int tid = threadIdx.x;
    int ty = tid >> 4, tx = tid & 15;

    #pragma unroll
    for (int u = 0; u < 4; u++) {
        int idx = tid + u * 256;
        int r = idx >> 4;
        int c4 = (idx & 15) * 4;
        const float* qsrc = qkv + (size_t)(b * TT + t0 + r) * (3 * CC) + h * HD + c4;
        float4 qv = *(const float4*)qsrc;
        Qt[c4 + 0][r] = qv.x;
        Qt[c4 + 1][r] = qv.y;
        Qt[c4 + 2][r] = qv.z;
        Qt[c4 + 3][r] = qv.w;
    }

    float m_i[4], l_i[4], acc[4][4];
    #pragma unroll
    for (int i = 0; i < 4; i++) {
        m_i[i] = -1e30f;
        l_i[i] = 0.f;
        #pragma unroll
        for (int j = 0; j < 4; j++) acc[i][j] = 0.f;
    }

    int nTiles = blockIdx.x + 1;
    for (int st = 0; st < nTiles; st++) {
        int s0 = st * 64;

        __syncthreads();
        #pragma unroll
        for (int u = 0; u < 4; u++) {
            int idx = tid + u * 256;
            int r = idx >> 4;
            int c4 = (idx & 15) * 4;
            const float* ksrc = qkv + (size_t)(b * TT + s0 + r) * (3 * CC) + CC + h * HD + c4;
            float4 kv = *(const float4*)ksrc;
            KPt[c4 + 0][r] = kv.x;
            KPt[c4 + 1][r] = kv.y;
            KPt[c4 + 2][r] = kv.z;
            KPt[c4 + 3][r] = kv.w;
            const float* vsrc = qkv + (size_t)(b * TT + s0 + r) * (3 * CC) + 2 * CC + h * HD + c4;
            *(float4*)&Vs[r][c4] = *(const float4*)vsrc;
        }
        __syncthreads();

        float S[4][4];
        #pragma unroll
        for (int i = 0; i < 4; i++)
            #pragma unroll
            for (int j = 0; j < 4; j++) S[i][j] = 0.f;

        #pragma unroll 8
        for (int d = 0; d < 64; d++) {
            float4 aq = *(float4*)&Qt[d][ty * 4];
            float4 bq = *(float4*)&KPt[d][tx * 4];
            float av[4] = {aq.x, aq.y, aq.z, aq.w};
            float bv[4] = {bq.x, bq.y, bq.z, bq.w};
            #pragma unroll
            for (int i = 0; i < 4; i++)
                #pragma unroll
                for (int j = 0; j < 4; j++) S[i][j] += av[i] * bv[j];
        }

        __syncthreads();

        const float scale = 0.125f;
        bool diag = (st == blockIdx.x);
        #pragma unroll
        for (int i = 0; i < 4; i++) {
            int t = t0 + ty * 4 + i;
            #pragma unroll
            for (int j = 0; j < 4; j++) {
                float v = S[i][j] * scale;
                if (diag && (s0 + tx * 4 + j > t)) v = -1e30f;
                S[i][j] = v;
            }
        }

        #pragma unroll
        for (int i = 0; i < 4; i++) {
            float rmax = fmaxf(fmaxf(S[i][0], S[i][1]), fmaxf(S[i][2], S[i][3]));
            #pragma unroll
            for (int o = 8; o > 0; o >>= 1)
                rmax = fmaxf(rmax, __shfl_xor_sync(0xffffffffu, rmax, o));
            float mnew = fmaxf(m_i[i], rmax);
            float alpha = __expf(m_i[i] - mnew);
            float rsum = 0.f;
            #pragma unroll
            for (int j = 0; j < 4; j++) {
                float p = __expf(S[i][j] - mnew);
                S[i][j] = p;
                rsum += p;
            }
            #pragma unroll
            for (int o = 8; o > 0; o >>= 1)
                rsum += __shfl_xor_sync(0xffffffffu, rsum, o);
            l_i[i] = l_i[i] * alpha + rsum;
            m_i[i] = mnew;
            #pragma unroll
            for (int j = 0; j < 4; j++) acc[i][j] *= alpha;
        }

        #pragma unroll
        for (int i = 0; i < 4; i++)
            #pragma unroll
            for (int j = 0; j < 4; j++)
                KPt[tx * 4 + j][ty * 4 + i] = S[i][j];
        __syncthreads();

        #pragma unroll 8
        for (int k = 0; k < 64; k++) {
            float4 ap = *(float4*)&KPt[k][ty * 4];
            float4 vv = *(float4*)&Vs[k][tx * 4];
            float av[4] = {ap.x, ap.y, ap.z, ap.w};
            float bv[4] = {vv.x, vv.y, vv.z, vv.w};
            #pragma unroll
            for (int i = 0; i < 4; i++)
                #pragma unroll
                for (int j = 0; j < 4; j++) acc[i][j] += av[i] * bv[j];
        }
    }

    #pragma unroll
    for (int i = 0; i < 4; i++) {
        float inv = 1.f / l_i[i];
        int t = t0 + ty * 4 + i;
        float* orow = y + (size_t)(b * TT + t) * CC + h * HD;
        #pragma unroll
        for (int j = 0; j < 4; j++) orow[tx * 4 + j] = acc[i][j] * inv;
    }
}

// ---------------- host launcher ----------------
extern "C" void kernel_launch(void* const* d_in, const int* in_sizes, int n_in,
                              void* d_out, int out_size) {
    (void)in_sizes; (void)n_in; (void)out_size;
    const int*   idx    = (const int*)  d_in[0];
    const float* wte    = (const float*)d_in[1];
    const float* wpe    = (const float*)d_in[2];
    const float* ln1_w  = (const float*)d_in[3];
    const float* ln1_b  = (const float*)d_in[4];
    const float* qkv_w  = (const float*)d_in[5];
    const float* qkv_b  = (const float*)d_in[6];
    const float* proj_w = (const float*)d_in[7];
    const float* proj_b = (const float*)d_in[8];
    const float* ln2_w  = (const float*)d_in[9];
    const float* ln2_b  = (const float*)d_in[10];
    const float* fc_w   = (const float*)d_in[11];
    const float* fc_b   = (const float*)d_in[12];
    const float* fc2_w  = (const float*)d_in[13];
    const float* fc2_b  = (const float*)d_in[14];
    const float* lnf_w  = (const float*)d_in[15];
    const float* lnf_b  = (const float*)d_in[16];
    const float* head_w = (const float*)d_in[17];
    float* out = (float*)d_out;

    float *x, *h, *qkv, *y, *m1;
    cudaGetSymbolAddress((void**)&x,   g_x);
    cudaGetSymbolAddress((void**)&h,   g_h);
    cudaGetSymbolAddress((void**)&qkv, g_qkv);
    cudaGetSymbolAddress((void**)&y,   g_y);
    cudaGetSymbolAddress((void**)&m1,  g_m1);

    embed_k<<<NTOK, 256>>>(idx, wte, wpe, x);

    for (int l = 0; l < LL; l++) {
        const float* l_ln1w  = ln1_w  + (size_t)l * CC;
        const float* l_ln1b  = ln1_b  + (size_t)l * CC;
        const float* l_qkvw  = qkv_w  + (size_t)l * CC * 3 * CC;
        const float* l_qkvb  = qkv_b  + (size_t)l * 3 * CC;
        const float* l_pw    = proj_w + (size_t)l * CC * CC;
        const float* l_pb    = proj_b + (size_t)l * CC;
        const float* l_ln2w  = ln2_w  + (size_t)l * CC;
        const float* l_ln2b  = ln2_b  + (size_t)l * CC;
        const float* l_fcw   = fc_w   + (size_t)l * CC * 4 * CC;
        const float* l_fcb   = fc_b   + (size_t)l * 4 * CC;
        const float* l_fc2w  = fc2_w  + (size_t)l * 4 * CC * CC;
        const float* l_fc2b  = fc2_b  + (size_t)l * CC;

        layernorm_k<<<NTOK, 256>>>(x, l_ln1w, l_ln1b, h);
        tgemm_k<true, false, false><<<dim3((3 * CC) / 128, NTOK / 128), 256>>>(
            h, l_qkvw, l_qkvb, nullptr, qkv, NTOK, 3 * CC, CC);
        flash_attn_k<<<dim3(TT / 64, BH), 256>>>(qkv, y);
        tgemm_k<true, false, true><<<dim3(CC / 128, NTOK / 128), 256>>>(
            y, l_pw, l_pb, x, x, NTOK, CC, CC);
        layernorm_k<<<NTOK, 256>>>(x, l_ln2w, l_ln2b, h);
        tgemm_k<true, true, false><<<dim3((4 * CC) / 128, NTOK / 128), 256>>>(
            h, l_fcw, l_fcb, nullptr, m1, NTOK, 4 * CC, CC);
        tgemm_k<true, false, true><<<dim3(CC / 128, NTOK / 128), 256>>>(
            m1, l_fc2w, l_fc2b, x, x, NTOK, CC, 4 * CC);
    }

    layernorm_k<<<NTOK, 256>>>(x, lnf_w, lnf_b, h);
    tgemm_k<false, false, false><<<dim3((VV + 127) / 128, NTOK / 128), 256>>>(
        h, head_w, nullptr, nullptr, out, NTOK, VV, CC);
}

// round 5
// speedup vs baseline: 2.2202x; 1.2434x over previous
#include <cuda_runtime.h>
#include <math.h>
#include <stdint.h>

// ---------------- dimensions ----------------
#define BB   2
#define TT   1024
#define CC   768
#define NH   12
#define HD   64
#define LL   4
#define VV   50257
#define NTOK 2048          // BB*TT
#define BH   24            // BB*NH

// ---------------- scratch (static device globals; no allocs) ----------------
__device__ float g_x  [NTOK * CC];
__device__ float g_h  [NTOK * CC];
__device__ float g_qkv[NTOK * 3 * CC];
__device__ float g_y  [NTOK * CC];
__device__ float g_m1 [NTOK * 4 * CC];

// ---------------- reduction helpers ----------------
__device__ __forceinline__ float warpReduceSum(float v) {
    #pragma unroll
    for (int o = 16; o > 0; o >>= 1) v += __shfl_xor_sync(0xffffffffu, v, o);
    return v;
}
__device__ float blockReduceSum(float v) {
    __shared__ float s[32];
    int lane = threadIdx.x & 31, wid = threadIdx.x >> 5;
    v = warpReduceSum(v);
    if (lane == 0) s[wid] = v;
    __syncthreads();
    int nw = blockDim.x >> 5;
    v = (threadIdx.x < nw) ? s[threadIdx.x] : 0.f;
    if (wid == 0) v = warpReduceSum(v);
    if (threadIdx.x == 0) s[0] = v;
    __syncthreads();
    v = s[0];
    __syncthreads();
    return v;
}

__device__ __forceinline__ float gelu_f(float x) {
    const float k = 0.7978845608028654f;  // sqrt(2/pi)
    float x3 = x * x * x;
    return 0.5f * x * (1.f + tanhf(k * (x + 0.044715f * x3)));
}

__device__ __forceinline__ uint32_t f2tf32(float x) {
    uint32_t r;
    asm("cvt.rna.tf32.f32 %0, %1;" : "=r"(r) : "f"(x));
    return r;
}

__device__ __forceinline__ void mma_tf32(float c[4],
                                         uint32_t a0, uint32_t a1, uint32_t a2, uint32_t a3,
                                         uint32_t b0, uint32_t b1) {
    asm volatile(
        "mma.sync.aligned.m16n8k8.row.col.f32.tf32.tf32.f32 "
        "{%0,%1,%2,%3}, {%4,%5,%6,%7}, {%8,%9}, {%0,%1,%2,%3};\n"
        : "+f"(c[0]), "+f"(c[1]), "+f"(c[2]), "+f"(c[3])
        : "r"(a0), "r"(a1), "r"(a2), "r"(a3), "r"(b0), "r"(b1));
}

// ---------------- cp.async helpers ----------------
__device__ __forceinline__ void cp16(uint32_t dst, const void* src) {
    asm volatile("cp.async.cg.shared.global [%0], [%1], 16;" :: "r"(dst), "l"(src));
}
__device__ __forceinline__ void cp4z(uint32_t dst, const void* src, int sz) {
    // 4-byte copy, zero-fill when sz==0
    asm volatile("cp.async.ca.shared.global [%0], [%1], 4, %2;"
                 :: "r"(dst), "l"(src), "r"(sz));
}
__device__ __forceinline__ void cp_commit() {
    asm volatile("cp.async.commit_group;");
}
__device__ __forceinline__ void cp_wait1() {
    asm volatile("cp.async.wait_group 1;");
}
__device__ __forceinline__ void cp_wait0() {
    asm volatile("cp.async.wait_group 0;");
}

// ---------------- embedding ----------------
__global__ void embed_k(const int* __restrict__ idx, const float* __restrict__ wte,
                        const float* __restrict__ wpe, float* __restrict__ x) {
    int row = blockIdx.x;              // b*TT + t
    int t = row & (TT - 1);
    int tok = idx[row];
    const float* we = wte + (size_t)tok * CC;
    const float* pe = wpe + (size_t)t * CC;
    float* o = x + (size_t)row * CC;
    for (int c = threadIdx.x; c < CC; c += blockDim.x) o[c] = we[c] + pe[c];
}

// ---------------- layernorm (block per row, 256 threads, 3 elems/thread) ----------------
__global__ void layernorm_k(const float* __restrict__ in, const float* __restrict__ w,
                            const float* __restrict__ b, float* __restrict__ out) {
    int row = blockIdx.x;
    const float* p = in + (size_t)row * CC;
    int tid = threadIdx.x;
    float v[3];
    float s = 0.f;
    #pragma unroll
    for (int i = 0; i < 3; i++) { v[i] = p[tid + i * 256]; s += v[i]; }
    float mean = blockReduceSum(s) * (1.f / (float)CC);
    float vs = 0.f;
    #pragma unroll
    for (int i = 0; i < 3; i++) { float d = v[i] - mean; vs += d * d; }
    float var = blockReduceSum(vs) * (1.f / (float)CC);
    float rstd = rsqrtf(var + 1e-5f);
    float* o = out + (size_t)row * CC;
    #pragma unroll
    for (int i = 0; i < 3; i++) {
        int c = tid + i * 256;
        o[c] = (v[i] - mean) * rstd * w[c] + b[c];
    }
}

// ---------------- TF32 tensor-core GEMM (cp.async double-buffered) ----------------
// C = epi(A[MxK] @ B[KxN]). 128x128 block tile, KT=32, 256 threads = 8 warps,
// warp grid 2(m) x 4(n), each warp 64x32 via 4x4 m16n8k8 MMAs.
// Smem holds RAW fp32 (cp.async-able); cvt to tf32 happens in registers.
// A smem: [m][k] stride 36 (conflict-free frag loads); B smem: [k][n] stride 132.
#define KT   32
#define SA   36
#define SB   132
#define ASZ  (128 * SA)            // floats
#define BSZ  (KT * SB)             // floats
#define STG  (ASZ + BSZ)           // floats per stage
#define GEMM_SMEM_BYTES (2 * STG * 4)

template <bool BIAS, bool GELU, bool RESID>
__global__ __launch_bounds__(256, 2) void tgemm_k(
    const float* __restrict__ A, const float* __restrict__ B,
    const float* __restrict__ bias, const float* __restrict__ resid,
    float* __restrict__ C, int M, int N, int K) {
    extern __shared__ float smem[];

    int tid = threadIdx.x;
    int lane = tid & 31;
    int wid = tid >> 5;
    int warp_m = wid >> 2;             // 0..1
    int warp_n = wid & 3;              // 0..3
    int lr = lane >> 2;                // 0..7
    int lc = lane & 3;                 // 0..3

    int row0 = blockIdx.y * 128;
    int col0 = blockIdx.x * 128;

    // cp.async mappings
    int aM  = tid >> 1;                // 0..127 (A row)
    int aK4 = (tid & 1) * 16;          // A k-chunk base (+u*4)
    int bK  = tid >> 3;                // 0..31 (B row)
    int bN4 = (tid & 7) * 4;           // B n-chunk base (+u*32)

    bool fullN = (col0 + 128 <= N);
    bool vecB  = fullN && ((N & 3) == 0);

    float acc[4][4][4];
    #pragma unroll
    for (int i = 0; i < 4; i++)
        #pragma unroll
        for (int j = 0; j < 4; j++)
            #pragma unroll
            for (int q = 0; q < 4; q++) acc[i][j][q] = 0.f;

    const float* aSrcBase = A + (size_t)(row0 + aM) * K + aK4;

    // ---- stage loader ----
    auto load_stage = [&](int kt, int s) {
        float* As = smem + s * STG;
        float* Bs = As + ASZ;
        // A tile: 128 x 32 raw fp32
        {
            uint32_t dst = (uint32_t)__cvta_generic_to_shared(&As[aM * SA + aK4]);
            const float* src = aSrcBase + kt;
            #pragma unroll
            for (int u = 0; u < 4; u++)
                cp16(dst + u * 16, src + u * 4);
        }
        // B tile: 32 x 128 raw fp32
        if (vecB) {
            uint32_t dst = (uint32_t)__cvta_generic_to_shared(&Bs[bK * SB + bN4]);
            const float* src = B + (size_t)(kt + bK) * N + col0 + bN4;
            #pragma unroll
            for (int u = 0; u < 4; u++)
                cp16(dst + u * 32 * 4, src + u * 32);
        } else {
            uint32_t dst = (uint32_t)__cvta_generic_to_shared(&Bs[bK * SB]);
            const float* src = B + (size_t)(kt + bK) * N;
            #pragma unroll
            for (int u = 0; u < 4; u++) {
                #pragma unroll
                for (int q = 0; q < 4; q++) {
                    int c = bN4 + u * 32 + q;
                    int ok = (col0 + c < N) ? 4 : 0;
                    const float* p = src + (ok ? (col0 + c) : 0);
                    cp4z(dst + c * 4, p, ok);
                }
            }
        }
    };

    int nIter = K / KT;
    load_stage(0, 0);
    cp_commit();

    for (int it = 0; it < nIter; it++) {
        if (it + 1 < nIter) {
            load_stage((it + 1) * KT, (it + 1) & 1);
            cp_commit();
            cp_wait1();
        } else {
            cp_wait0();
        }
        __syncthreads();

        const float* As = smem + (it & 1) * STG;
        const float* Bs = As + ASZ;

        #pragma unroll
        for (int ks = 0; ks < 4; ks++) {
            int k0 = ks * 8;
            uint32_t af[4][4];
            #pragma unroll
            for (int mt = 0; mt < 4; mt++) {
                int am = warp_m * 64 + mt * 16;
                af[mt][0] = f2tf32(As[(am + lr    ) * SA + k0 + lc    ]);
                af[mt][1] = f2tf32(As[(am + lr + 8) * SA + k0 + lc    ]);
                af[mt][2] = f2tf32(As[(am + lr    ) * SA + k0 + lc + 4]);
                af[mt][3] = f2tf32(As[(am + lr + 8) * SA + k0 + lc + 4]);
            }
            #pragma unroll
            for (int nt = 0; nt < 4; nt++) {
                int bn = warp_n * 32 + nt * 8;
                uint32_t b0 = f2tf32(Bs[(k0 + lc    ) * SB + bn + lr]);
                uint32_t b1 = f2tf32(Bs[(k0 + 4 + lc) * SB + bn + lr]);
                #pragma unroll
                for (int mt = 0; mt < 4; mt++)
                    mma_tf32(acc[mt][nt], af[mt][0], af[mt][1], af[mt][2], af[mt][3], b0, b1);
            }
        }
        __syncthreads();
    }

    // ---- epilogue ----
    #pragma unroll
    for (int mt = 0; mt < 4; mt++) {
        int rbase = row0 + warp_m * 64 + mt * 16 + lr;
        #pragma unroll
        for (int nt = 0; nt < 4; nt++) {
            int cbase = col0 + warp_n * 32 + nt * 8 + lc * 2;
            #pragma unroll
            for (int half = 0; half < 2; half++) {
                int r = rbase + half * 8;
                #pragma unroll
                for (int q = 0; q < 2; q++) {
                    int c = cbase + q;
                    if (c < N) {
                        float v = acc[mt][nt][half * 2 + q];
                        if (BIAS) v += bias[c];
                        if (GELU) v = gelu_f(v);
                        if (RESID) v += resid[(size_t)r * N + c];
                        C[(size_t)r * N + c] = v;
                    }
                }
            }
        }
    }
}

// ---------------- fused flash attention (fp32) ----------------
// grid (TT/64, BH), block 256. 64 query rows per block, online softmax over
// causal s-tiles of 64.
__global__ __launch_bounds__(256) void flash_attn_k(const float* __restrict__ qkv,
                                                    float* __restrict__ y) {
    __shared__ float Qt [64][64];   // [d][t]
    __shared__ float KPt[64][64];   // phase 1: K^T [d][s]; phase 2: P^T [s][t]
    __shared__ float Vs [64][64];   // [s][d]

    int bh = blockIdx.y;
    int b = bh / NH, h = bh % NH;
    int t0 = blockIdx.x * 64;
    int tid = threadIdx.x;
    int ty = tid >> 4, tx = tid & 15;

    #pragma unroll
    for (int u = 0; u < 4; u++) {
        int idx = tid + u * 256;
        int r = idx >> 4;
        int c4 = (idx & 15) * 4;
        const float* qsrc = qkv + (size_t)(b * TT + t0 + r) * (3 * CC) + h * HD + c4;
        float4 qv = *(const float4*)qsrc;
        Qt[c4 + 0][r] = qv.x;
        Qt[c4 + 1][r] = qv.y;
        Qt[c4 + 2][r] = qv.z;
        Qt[c4 + 3][r] = qv.w;
    }

    float m_i[4], l_i[4], acc[4][4];
    #pragma unroll
    for (int i = 0; i < 4; i++) {
        m_i[i] = -1e30f;
        l_i[i] = 0.f;
        #pragma unroll
        for (int j = 0; j < 4; j++) acc[i][j] = 0.f;
    }

    int nTiles = blockIdx.x + 1;
    for (int st = 0; st < nTiles; st++) {
        int s0 = st * 64;

        __syncthreads();
        #pragma unroll
        for (int u = 0; u < 4; u++) {
            int idx = tid + u * 256;
            int r = idx >> 4;
            int c4 = (idx & 15) * 4;
            const float* ksrc = qkv + (size_t)(b * TT + s0 + r) * (3 * CC) + CC + h * HD + c4;
            float4 kv = *(const float4*)ksrc;
            KPt[c4 + 0][r] = kv.x;
            KPt[c4 + 1][r] = kv.y;
            KPt[c4 + 2][r] = kv.z;
            KPt[c4 + 3][r] = kv.w;
            const float* vsrc = qkv + (size_t)(b * TT + s0 + r) * (3 * CC) + 2 * CC + h * HD + c4;
            *(float4*)&Vs[r][c4] = *(const float4*)vsrc;
        }
        __syncthreads();

        float S[4][4];
        #pragma unroll
        for (int i = 0; i < 4; i++)
            #pragma unroll
            for (int j = 0; j < 4; j++) S[i][j] = 0.f;

        #pragma unroll 8
        for (int d = 0; d < 64; d++) {
            float4 aq = *(float4*)&Qt[d][ty * 4];
            float4 bq = *(float4*)&KPt[d][tx * 4];
            float av[4] = {aq.x, aq.y, aq.z, aq.w};
            float bv[4] = {bq.x, bq.y, bq.z, bq.w};
            #pragma unroll
            for (int i = 0; i < 4; i++)
                #pragma unroll
                for (int j = 0; j < 4; j++) S[i][j] += av[i] * bv[j];
        }

        __syncthreads();

        const float scale = 0.125f;
        bool diag = (st == blockIdx.x);
        #pragma unroll
        for (int i = 0; i < 4; i++) {
            int t = t0 + ty * 4 + i;
            #pragma unroll
            for (int j = 0; j < 4; j++) {
                float v = S[i][j] * scale;
                if (diag && (s0 + tx * 4 + j > t)) v = -1e30f;
                S[i][j] = v;
            }
        }

        #pragma unroll
        for (int i = 0; i < 4; i++) {
            float rmax = fmaxf(fmaxf(S[i][0], S[i][1]), fmaxf(S[i][2], S[i][3]));
            #pragma unroll
            for (int o = 8; o > 0; o >>= 1)
                rmax = fmaxf(rmax, __shfl_xor_sync(0xffffffffu, rmax, o));
            float mnew = fmaxf(m_i[i], rmax);
            float alpha = __expf(m_i[i] - mnew);
            float rsum = 0.f;
            #pragma unroll
            for (int j = 0; j < 4; j++) {
                float p = __expf(S[i][j] - mnew);
                S[i][j] = p;
                rsum += p;
            }
            #pragma unroll
            for (int o = 8; o > 0; o >>= 1)
                rsum += __shfl_xor_sync(0xffffffffu, rsum, o);
            l_i[i] = l_i[i] * alpha + rsum;
            m_i[i] = mnew;
            #pragma unroll
            for (int j = 0; j < 4; j++) acc[i][j] *= alpha;
        }

        #pragma unroll
        for (int i = 0; i < 4; i++)
            #pragma unroll
            for (int j = 0; j < 4; j++)
                KPt[tx * 4 + j][ty * 4 + i] = S[i][j];
        __syncthreads();

        #pragma unroll 8
        for (int k = 0; k < 64; k++) {
            float4 ap = *(float4*)&KPt[k][ty * 4];
            float4 vv = *(float4*)&Vs[k][tx * 4];
            float av[4] = {ap.x, ap.y, ap.z, ap.w};
            float bv[4] = {vv.x, vv.y, vv.z, vv.w};
            #pragma unroll
            for (int i = 0; i < 4; i++)
                #pragma unroll
                for (int j = 0; j < 4; j++) acc[i][j] += av[i] * bv[j];
        }
    }

    #pragma unroll
    for (int i = 0; i < 4; i++) {
        float inv = 1.f / l_i[i];
        int t = t0 + ty * 4 + i;
        float* orow = y + (size_t)(b * TT + t) * CC + h * HD;
        #pragma unroll
        for (int j = 0; j < 4; j++) orow[tx * 4 + j] = acc[i][j] * inv;
    }
}

// ---------------- host launcher ----------------
extern "C" void kernel_launch(void* const* d_in, const int* in_sizes, int n_in,
                              void* d_out, int out_size) {
    (void)in_sizes; (void)n_in; (void)out_size;
    const int*   idx    = (const int*)  d_in[0];
    const float* wte    = (const float*)d_in[1];
    const float* wpe    = (const float*)d_in[2];
    const float* ln1_w  = (const float*)d_in[3];
    const float* ln1_b  = (const float*)d_in[4];
    const float* qkv_w  = (const float*)d_in[5];
    const float* qkv_b  = (const float*)d_in[6];
    const float* proj_w = (const float*)d_in[7];
    const float* proj_b = (const float*)d_in[8];
    const float* ln2_w  = (const float*)d_in[9];
    const float* ln2_b  = (const float*)d_in[10];
    const float* fc_w   = (const float*)d_in[11];
    const float* fc_b   = (const float*)d_in[12];
    const float* fc2_w  = (const float*)d_in[13];
    const float* fc2_b  = (const float*)d_in[14];
    const float* lnf_w  = (const float*)d_in[15];
    const float* lnf_b  = (const float*)d_in[16];
    const float* head_w = (const float*)d_in[17];
    float* out = (float*)d_out;

    float *x, *h, *qkv, *y, *m1;
    cudaGetSymbolAddress((void**)&x,   g_x);
    cudaGetSymbolAddress((void**)&h,   g_h);
    cudaGetSymbolAddress((void**)&qkv, g_qkv);
    cudaGetSymbolAddress((void**)&y,   g_y);
    cudaGetSymbolAddress((void**)&m1,  g_m1);

    // allow 70KB dynamic smem on all tgemm instantiations (idempotent)
    cudaFuncSetAttribute(tgemm_k<true,  false, false>, cudaFuncAttributeMaxDynamicSharedMemorySize, GEMM_SMEM_BYTES);
    cudaFuncSetAttribute(tgemm_k<true,  false, true >, cudaFuncAttributeMaxDynamicSharedMemorySize, GEMM_SMEM_BYTES);
    cudaFuncSetAttribute(tgemm_k<true,  true,  false>, cudaFuncAttributeMaxDynamicSharedMemorySize, GEMM_SMEM_BYTES);
    cudaFuncSetAttribute(tgemm_k<false, false, false>, cudaFuncAttributeMaxDynamicSharedMemorySize, GEMM_SMEM_BYTES);

    embed_k<<<NTOK, 256>>>(idx, wte, wpe, x);

    for (int l = 0; l < LL; l++) {
        const float* l_ln1w  = ln1_w  + (size_t)l * CC;
        const float* l_ln1b  = ln1_b  + (size_t)l * CC;
        const float* l_qkvw  = qkv_w  + (size_t)l * CC * 3 * CC;
        const float* l_qkvb  = qkv_b  + (size_t)l * 3 * CC;
        const float* l_pw    = proj_w + (size_t)l * CC * CC;
        const float* l_pb    = proj_b + (size_t)l * CC;
        const float* l_ln2w  = ln2_w  + (size_t)l * CC;
        const float* l_ln2b  = ln2_b  + (size_t)l * CC;
        const float* l_fcw   = fc_w   + (size_t)l * CC * 4 * CC;
        const float* l_fcb   = fc_b   + (size_t)l * 4 * CC;
        const float* l_fc2w  = fc2_w  + (size_t)l * 4 * CC * CC;
        const float* l_fc2b  = fc2_b  + (size_t)l * CC;

        layernorm_k<<<NTOK, 256>>>(x, l_ln1w, l_ln1b, h);
        tgemm_k<true, false, false><<<dim3((3 * CC) / 128, NTOK / 128), 256, GEMM_SMEM_BYTES>>>(
            h, l_qkvw, l_qkvb, nullptr, qkv, NTOK, 3 * CC, CC);
        flash_attn_k<<<dim3(TT / 64, BH), 256>>>(qkv, y);
        tgemm_k<true, false, true><<<dim3(CC / 128, NTOK / 128), 256, GEMM_SMEM_BYTES>>>(
            y, l_pw, l_pb, x, x, NTOK, CC, CC);
        layernorm_k<<<NTOK, 256>>>(x, l_ln2w, l_ln2b, h);
        tgemm_k<true, true, false><<<dim3((4 * CC) / 128, NTOK / 128), 256, GEMM_SMEM_BYTES>>>(
            h, l_fcw, l_fcb, nullptr, m1, NTOK, 4 * CC, CC);
        tgemm_k<true, false, true><<<dim3(CC / 128, NTOK / 128), 256, GEMM_SMEM_BYTES>>>(
            m1, l_fc2w, l_fc2b, x, x, NTOK, CC, 4 * CC);
    }

    layernorm_k<<<NTOK, 256>>>(x, lnf_w, lnf_b, h);
    tgemm_k<false, false, false><<<dim3((VV + 127) / 128, NTOK / 128), 256, GEMM_SMEM_BYTES>>>(
        h, head_w, nullptr, nullptr, out, NTOK, VV, CC);
}

// round 6
// speedup vs baseline: 2.5781x; 1.1612x over previous
#include <cuda_runtime.h>
#include <math.h>
#include <stdint.h>

// ---------------- dimensions ----------------
#define BB   2
#define TT   1024
#define CC   768
#define NH   12
#define HD   64
#define LL   4
#define VV   50257
#define NPAD 50304         // 393 * 128, head_w padded columns
#define NTOK 2048          // BB*TT
#define BH   24            // BB*NH

// ---------------- scratch (static device globals; no allocs) ----------------
__device__ float g_x  [NTOK * CC];
__device__ float g_h  [NTOK * CC];
__device__ float g_qkv[NTOK * 3 * CC];
__device__ float g_y  [NTOK * CC];
__device__ float g_m1 [NTOK * 4 * CC];
__device__ float g_wpad[(size_t)CC * NPAD];   // padded head weights (~154.5 MB)

// ---------------- reduction helpers ----------------
__device__ __forceinline__ float warpReduceSum(float v) {
    #pragma unroll
    for (int o = 16; o > 0; o >>= 1) v += __shfl_xor_sync(0xffffffffu, v, o);
    return v;
}
__device__ float blockReduceSum(float v) {
    __shared__ float s[32];
    int lane = threadIdx.x & 31, wid = threadIdx.x >> 5;
    v = warpReduceSum(v);
    if (lane == 0) s[wid] = v;
    __syncthreads();
    int nw = blockDim.x >> 5;
    v = (threadIdx.x < nw) ? s[threadIdx.x] : 0.f;
    if (wid == 0) v = warpReduceSum(v);
    if (threadIdx.x == 0) s[0] = v;
    __syncthreads();
    v = s[0];
    __syncthreads();
    return v;
}

__device__ __forceinline__ float gelu_f(float x) {
    const float k = 0.7978845608028654f;  // sqrt(2/pi)
    float x3 = x * x * x;
    return 0.5f * x * (1.f + tanhf(k * (x + 0.044715f * x3)));
}

__device__ __forceinline__ uint32_t f2tf32(float x) {
    uint32_t r;
    asm("cvt.rna.tf32.f32 %0, %1;" : "=r"(r) : "f"(x));
    return r;
}

__device__ __forceinline__ void mma_tf32(float c[4],
                                         uint32_t a0, uint32_t a1, uint32_t a2, uint32_t a3,
                                         uint32_t b0, uint32_t b1) {
    asm volatile(
        "mma.sync.aligned.m16n8k8.row.col.f32.tf32.tf32.f32 "
        "{%0,%1,%2,%3}, {%4,%5,%6,%7}, {%8,%9}, {%0,%1,%2,%3};\n"
        : "+f"(c[0]), "+f"(c[1]), "+f"(c[2]), "+f"(c[3])
        : "r"(a0), "r"(a1), "r"(a2), "r"(a3), "r"(b0), "r"(b1));
}

// ---------------- cp.async helpers ----------------
__device__ __forceinline__ void cp16(uint32_t dst, const void* src) {
    asm volatile("cp.async.cg.shared.global [%0], [%1], 16;" :: "r"(dst), "l"(src));
}
__device__ __forceinline__ void cp_commit() {
    asm volatile("cp.async.commit_group;");
}
__device__ __forceinline__ void cp_wait1() {
    asm volatile("cp.async.wait_group 1;");
}
__device__ __forceinline__ void cp_wait0() {
    asm volatile("cp.async.wait_group 0;");
}

// ---------------- head weight padding: [768][50257] -> [768][50304] ----------------
__global__ void pad_head_k(const float* __restrict__ w, float* __restrict__ wp) {
    size_t idx = (size_t)blockIdx.x * blockDim.x + threadIdx.x;
    size_t base = idx * 4;
    const size_t tot = (size_t)CC * NPAD;
    if (base >= tot) return;
    int r = (int)(base / NPAD);
    int c = (int)(base % NPAD);
    const float* src = w + (size_t)r * VV;
    float4 v;
    v.x = (c + 0 < VV) ? src[c + 0] : 0.f;
    v.y = (c + 1 < VV) ? src[c + 1] : 0.f;
    v.z = (c + 2 < VV) ? src[c + 2] : 0.f;
    v.w = (c + 3 < VV) ? src[c + 3] : 0.f;
    *(float4*)&wp[base] = v;
}

// ---------------- embedding ----------------
__global__ void embed_k(const int* __restrict__ idx, const float* __restrict__ wte,
                        const float* __restrict__ wpe, float* __restrict__ x) {
    int row = blockIdx.x;              // b*TT + t
    int t = row & (TT - 1);
    int tok = idx[row];
    const float* we = wte + (size_t)tok * CC;
    const float* pe = wpe + (size_t)t * CC;
    float* o = x + (size_t)row * CC;
    for (int c = threadIdx.x; c < CC; c += blockDim.x) o[c] = we[c] + pe[c];
}

// ---------------- layernorm (block per row, 256 threads, 3 elems/thread) ----------------
__global__ void layernorm_k(const float* __restrict__ in, const float* __restrict__ w,
                            const float* __restrict__ b, float* __restrict__ out) {
    int row = blockIdx.x;
    const float* p = in + (size_t)row * CC;
    int tid = threadIdx.x;
    float v[3];
    float s = 0.f;
    #pragma unroll
    for (int i = 0; i < 3; i++) { v[i] = p[tid + i * 256]; s += v[i]; }
    float mean = blockReduceSum(s) * (1.f / (float)CC);
    float vs = 0.f;
    #pragma unroll
    for (int i = 0; i < 3; i++) { float d = v[i] - mean; vs += d * d; }
    float var = blockReduceSum(vs) * (1.f / (float)CC);
    float rstd = rsqrtf(var + 1e-5f);
    float* o = out + (size_t)row * CC;
    #pragma unroll
    for (int i = 0; i < 3; i++) {
        int c = tid + i * 256;
        o[c] = (v[i] - mean) * rstd * w[c] + b[c];
    }
}

// ---------------- TF32 tensor-core GEMM (cp.async double-buffered) ----------------
// C[M x Nout] = epi(A[M x K] @ B[K x ldB] restricted to Nout cols).
// Block tile (32*MT) x 128, KT=32, 256 threads = 8 warps, warp grid 2(m) x 4(n),
// each warp (MT*16) x 32 via MT x 4 m16n8k8 MMAs.
// ldB (B columns) MUST be a multiple of 128 and grid.x = ldB/128 (all loads full,
// 16B aligned). Output writes are bounded by Nout.
// Smem: raw fp32, A [m][k] stride 36, B [k][n] stride 132.
#define KT   32
#define SA   36
#define SB   132
#define BSZ  (KT * SB)

template <int MT, bool BIAS, bool GELU, bool RESID>
__global__ __launch_bounds__(256, 2) void tgemm_k(
    const float* __restrict__ A, const float* __restrict__ B,
    const float* __restrict__ bias, const float* __restrict__ resid,
    float* __restrict__ C, int M, int Nout, int ldB, int K) {
    extern __shared__ float smem[];

    constexpr int ROWS = 32 * MT;          // A rows per block
    constexpr int ASZ  = ROWS * SA;        // floats
    constexpr int STG  = ASZ + BSZ;        // floats per stage
    constexpr int TPR  = 256 / ROWS;       // threads per A row
    constexpr int KCH  = 32 / TPR;         // k floats per thread
    constexpr int NCPA = KCH / 4;          // cp16 per thread for A

    int tid = threadIdx.x;
    int lane = tid & 31;
    int wid = tid >> 5;
    int warp_m = wid >> 2;             // 0..1
    int warp_n = wid & 3;              // 0..3
    int lr = lane >> 2;                // 0..7
    int lc = lane & 3;                 // 0..3

    int row0 = blockIdx.y * ROWS;
    int col0 = blockIdx.x * 128;

    // cp.async mappings
    int aM  = tid / TPR;               // A row within tile
    int aK4 = (tid % TPR) * KCH;       // A k base
    int bK  = tid >> 3;                // 0..31 (B row)
    int bN4 = (tid & 7) * 4;           // B n base (+u*32)

    float acc[MT][4][4];
    #pragma unroll
    for (int i = 0; i < MT; i++)
        #pragma unroll
        for (int j = 0; j < 4; j++)
            #pragma unroll
            for (int q = 0; q < 4; q++) acc[i][j][q] = 0.f;

    const float* aSrcBase = A + (size_t)(row0 + aM) * K + aK4;
    const float* bSrcBase = B + (size_t)bK * ldB + col0 + bN4;

    auto load_stage = [&](int kt, int s) {
        float* As = smem + s * STG;
        float* Bs = As + ASZ;
        {
            uint32_t dst = (uint32_t)__cvta_generic_to_shared(&As[aM * SA + aK4]);
            const float* src = aSrcBase + kt;
            #pragma unroll
            for (int u = 0; u < NCPA; u++)
                cp16(dst + u * 16, src + u * 4);
        }
        {
            uint32_t dst = (uint32_t)__cvta_generic_to_shared(&Bs[bK * SB + bN4]);
            const float* src = bSrcBase + (size_t)kt * ldB;
            #pragma unroll
            for (int u = 0; u < 4; u++)
                cp16(dst + u * 32 * 4, src + u * 32);
        }
    };

    int nIter = K / KT;
    load_stage(0, 0);
    cp_commit();

    for (int it = 0; it < nIter; it++) {
        if (it + 1 < nIter) {
            load_stage((it + 1) * KT, (it + 1) & 1);
            cp_commit();
            cp_wait1();
        } else {
            cp_wait0();
        }
        __syncthreads();

        const float* As = smem + (it & 1) * STG;
        const float* Bs = As + ASZ;

        #pragma unroll
        for (int ks = 0; ks < 4; ks++) {
            int k0 = ks * 8;
            uint32_t af[MT][4];
            #pragma unroll
            for (int mt = 0; mt < MT; mt++) {
                int am = warp_m * (MT * 16) + mt * 16;
                af[mt][0] = f2tf32(As[(am + lr    ) * SA + k0 + lc    ]);
                af[mt][1] = f2tf32(As[(am + lr + 8) * SA + k0 + lc    ]);
                af[mt][2] = f2tf32(As[(am + lr    ) * SA + k0 + lc + 4]);
                af[mt][3] = f2tf32(As[(am + lr + 8) * SA + k0 + lc + 4]);
            }
            #pragma unroll
            for (int nt = 0; nt < 4; nt++) {
                int bn = warp_n * 32 + nt * 8;
                uint32_t b0 = f2tf32(Bs[(k0 + lc    ) * SB + bn + lr]);
                uint32_t b1 = f2tf32(Bs[(k0 + 4 + lc) * SB + bn + lr]);
                #pragma unroll
                for (int mt = 0; mt < MT; mt++)
                    mma_tf32(acc[mt][nt], af[mt][0], af[mt][1], af[mt][2], af[mt][3], b0, b1);
            }
        }
        __syncthreads();
    }

    // ---- epilogue ----
    #pragma unroll
    for (int mt = 0; mt < MT; mt++) {
        int rbase = row0 + warp_m * (MT * 16) + mt * 16 + lr;
        #pragma unroll
        for (int nt = 0; nt < 4; nt++) {
            int cbase = col0 + warp_n * 32 + nt * 8 + lc * 2;
            #pragma unroll
            for (int half = 0; half < 2; half++) {
                int r = rbase + half * 8;
                #pragma unroll
                for (int q = 0; q < 2; q++) {
                    int c = cbase + q;
                    if (c < Nout) {
                        float v = acc[mt][nt][half * 2 + q];
                        if (BIAS) v += bias[c];
                        if (GELU) v = gelu_f(v);
                        if (RESID) v += resid[(size_t)r * Nout + c];
                        C[(size_t)r * Nout + c] = v;
                    }
                }
            }
        }
    }
}

#define GEMM_SMEM_BYTES(MT) (2 * ((32 * (MT)) * SA + BSZ) * 4)

// ---------------- fused flash attention (fp32) ----------------
// grid (TT/64, BH), block 256. 64 query rows per block, online softmax over
// causal s-tiles of 64.
__global__ __launch_bounds__(256) void flash_attn_k(const float* __restrict__ qkv,
                                                    float* __restrict__ y) {
    __shared__ float Qt [64][64];   // [d][t]
    __shared__ float KPt[64][64];   // phase 1: K^T [d][s]; phase 2: P^T [s][t]
    __shared__ float Vs [64][64];   // [s][d]

    int bh = blockIdx.y;
    int b = bh / NH, h = bh % NH;
    int t0 = blockIdx.x * 64;
    int tid = threadIdx.x;
    int ty = tid >> 4, tx = tid & 15;

    #pragma unroll
    for (int u = 0; u < 4; u++) {
        int idx = tid + u * 256;
        int r = idx >> 4;
        int c4 = (idx & 15) * 4;
        const float* qsrc = qkv + (size_t)(b * TT + t0 + r) * (3 * CC) + h * HD + c4;
        float4 qv = *(const float4*)qsrc;
        Qt[c4 + 0][r] = qv.x;
        Qt[c4 + 1][r] = qv.y;
        Qt[c4 + 2][r] = qv.z;
        Qt[c4 + 3][r] = qv.w;
    }

    float m_i[4], l_i[4], acc[4][4];
    #pragma unroll
    for (int i = 0; i < 4; i++) {
        m_i[i] = -1e30f;
        l_i[i] = 0.f;
        #pragma unroll
        for (int j = 0; j < 4; j++) acc[i][j] = 0.f;
    }

    int nTiles = blockIdx.x + 1;
    for (int st = 0; st < nTiles; st++) {
        int s0 = st * 64;

        __syncthreads();
        #pragma unroll
        for (int u = 0; u < 4; u++) {
            int idx = tid + u * 256;
            int r = idx >> 4;
            int c4 = (idx & 15) * 4;
            const float* ksrc = qkv + (size_t)(b * TT + s0 + r) * (3 * CC) + CC + h * HD + c4;
            float4 kv = *(const float4*)ksrc;
            KPt[c4 + 0][r] = kv.x;
            KPt[c4 + 1][r] = kv.y;
            KPt[c4 + 2][r] = kv.z;
            KPt[c4 + 3][r] = kv.w;
            const float* vsrc = qkv + (size_t)(b * TT + s0 + r) * (3 * CC) + 2 * CC + h * HD + c4;
            *(float4*)&Vs[r][c4] = *(const float4*)vsrc;
        }
        __syncthreads();

        float S[4][4];
        #pragma unroll
        for (int i = 0; i < 4; i++)
            #pragma unroll
            for (int j = 0; j < 4; j++) S[i][j] = 0.f;

        #pragma unroll 8
        for (int d = 0; d < 64; d++) {
            float4 aq = *(float4*)&Qt[d][ty * 4];
            float4 bq = *(float4*)&KPt[d][tx * 4];
            float av[4] = {aq.x, aq.y, aq.z, aq.w};
            float bv[4] = {bq.x, bq.y, bq.z, bq.w};
            #pragma unroll
            for (int i = 0; i < 4; i++)
                #pragma unroll
                for (int j = 0; j < 4; j++) S[i][j] += av[i] * bv[j];
        }

        __syncthreads();

        const float scale = 0.125f;
        bool diag = (st == blockIdx.x);
        #pragma unroll
        for (int i = 0; i < 4; i++) {
            int t = t0 + ty * 4 + i;
            #pragma unroll
            for (int j = 0; j < 4; j++) {
                float v = S[i][j] * scale;
                if (diag && (s0 + tx * 4 + j > t)) v = -1e30f;
                S[i][j] = v;
            }
        }

        #pragma unroll
        for (int i = 0; i < 4; i++) {
            float rmax = fmaxf(fmaxf(S[i][0], S[i][1]), fmaxf(S[i][2], S[i][3]));
            #pragma unroll
            for (int o = 8; o > 0; o >>= 1)
                rmax = fmaxf(rmax, __shfl_xor_sync(0xffffffffu, rmax, o));
            float mnew = fmaxf(m_i[i], rmax);
            float alpha = __expf(m_i[i] - mnew);
            float rsum = 0.f;
            #pragma unroll
            for (int j = 0; j < 4; j++) {
                float p = __expf(S[i][j] - mnew);
                S[i][j] = p;
                rsum += p;
            }
            #pragma unroll
            for (int o = 8; o > 0; o >>= 1)
                rsum += __shfl_xor_sync(0xffffffffu, rsum, o);
            l_i[i] = l_i[i] * alpha + rsum;
            m_i[i] = mnew;
            #pragma unroll
            for (int j = 0; j < 4; j++) acc[i][j] *= alpha;
        }

        #pragma unroll
        for (int i = 0; i < 4; i++)
            #pragma unroll
            for (int j = 0; j < 4; j++)
                KPt[tx * 4 + j][ty * 4 + i] = S[i][j];
        __syncthreads();

        #pragma unroll 8
        for (int k = 0; k < 64; k++) {
            float4 ap = *(float4*)&KPt[k][ty * 4];
            float4 vv = *(float4*)&Vs[k][tx * 4];
            float av[4] = {ap.x, ap.y, ap.z, ap.w};
            float bv[4] = {vv.x, vv.y, vv.z, vv.w};
            #pragma unroll
            for (int i = 0; i < 4; i++)
                #pragma unroll
                for (int j = 0; j < 4; j++) acc[i][j] += av[i] * bv[j];
        }
    }

    #pragma unroll
    for (int i = 0; i < 4; i++) {
        float inv = 1.f / l_i[i];
        int t = t0 + ty * 4 + i;
        float* orow = y + (size_t)(b * TT + t) * CC + h * HD;
        #pragma unroll
        for (int j = 0; j < 4; j++) orow[tx * 4 + j] = acc[i][j] * inv;
    }
}

// ---------------- host launcher ----------------
extern "C" void kernel_launch(void* const* d_in, const int* in_sizes, int n_in,
                              void* d_out, int out_size) {
    (void)in_sizes; (void)n_in; (void)out_size;
    const int*   idx    = (const int*)  d_in[0];
    const float* wte    = (const float*)d_in[1];
    const float* wpe    = (const float*)d_in[2];
    const float* ln1_w  = (const float*)d_in[3];
    const float* ln1_b  = (const float*)d_in[4];
    const float* qkv_w  = (const float*)d_in[5];
    const float* qkv_b  = (const float*)d_in[6];
    const float* proj_w = (const float*)d_in[7];
    const float* proj_b = (const float*)d_in[8];
    const float* ln2_w  = (const float*)d_in[9];
    const float* ln2_b  = (const float*)d_in[10];
    const float* fc_w   = (const float*)d_in[11];
    const float* fc_b   = (const float*)d_in[12];
    const float* fc2_w  = (const float*)d_in[13];
    const float* fc2_b  = (const float*)d_in[14];
    const float* lnf_w  = (const float*)d_in[15];
    const float* lnf_b  = (const float*)d_in[16];
    const float* head_w = (const float*)d_in[17];
    float* out = (float*)d_out;

    float *x, *h, *qkv, *y, *m1, *wpad;
    cudaGetSymbolAddress((void**)&x,    g_x);
    cudaGetSymbolAddress((void**)&h,    g_h);
    cudaGetSymbolAddress((void**)&qkv,  g_qkv);
    cudaGetSymbolAddress((void**)&y,    g_y);
    cudaGetSymbolAddress((void**)&m1,   g_m1);
    cudaGetSymbolAddress((void**)&wpad, g_wpad);

    cudaFuncSetAttribute(tgemm_k<4, true,  false, false>, cudaFuncAttributeMaxDynamicSharedMemorySize, GEMM_SMEM_BYTES(4));
    cudaFuncSetAttribute(tgemm_k<4, true,  true,  false>, cudaFuncAttributeMaxDynamicSharedMemorySize, GEMM_SMEM_BYTES(4));
    cudaFuncSetAttribute(tgemm_k<4, false, false, false>, cudaFuncAttributeMaxDynamicSharedMemorySize, GEMM_SMEM_BYTES(4));
    cudaFuncSetAttribute(tgemm_k<2, true,  false, true >, cudaFuncAttributeMaxDynamicSharedMemorySize, GEMM_SMEM_BYTES(2));

    // pad head weights into [CC][NPAD]
    {
        size_t tot4 = ((size_t)CC * NPAD) / 4;
        int blocks = (int)((tot4 + 255) / 256);
        pad_head_k<<<blocks, 256>>>(head_w, wpad);
    }

    embed_k<<<NTOK, 256>>>(idx, wte, wpe, x);

    for (int l = 0; l < LL; l++) {
        const float* l_ln1w  = ln1_w  + (size_t)l * CC;
        const float* l_ln1b  = ln1_b  + (size_t)l * CC;
        const float* l_qkvw  = qkv_w  + (size_t)l * CC * 3 * CC;
        const float* l_qkvb  = qkv_b  + (size_t)l * 3 * CC;
        const float* l_pw    = proj_w + (size_t)l * CC * CC;
        const float* l_pb    = proj_b + (size_t)l * CC;
        const float* l_ln2w  = ln2_w  + (size_t)l * CC;
        const float* l_ln2b  = ln2_b  + (size_t)l * CC;
        const float* l_fcw   = fc_w   + (size_t)l * CC * 4 * CC;
        const float* l_fcb   = fc_b   + (size_t)l * 4 * CC;
        const float* l_fc2w  = fc2_w  + (size_t)l * 4 * CC * CC;
        const float* l_fc2b  = fc2_b  + (size_t)l * CC;

        layernorm_k<<<NTOK, 256>>>(x, l_ln1w, l_ln1b, h);
        tgemm_k<4, true, false, false><<<dim3((3 * CC) / 128, NTOK / 128), 256, GEMM_SMEM_BYTES(4)>>>(
            h, l_qkvw, l_qkvb, nullptr, qkv, NTOK, 3 * CC, 3 * CC, CC);
        flash_attn_k<<<dim3(TT / 64, BH), 256>>>(qkv, y);
        tgemm_k<2, true, false, true><<<dim3(CC / 128, NTOK / 64), 256, GEMM_SMEM_BYTES(2)>>>(
            y, l_pw, l_pb, x, x, NTOK, CC, CC, CC);
        layernorm_k<<<NTOK, 256>>>(x, l_ln2w, l_ln2b, h);
        tgemm_k<4, true, true, false><<<dim3((4 * CC) / 128, NTOK / 128), 256, GEMM_SMEM_BYTES(4)>>>(
            h, l_fcw, l_fcb, nullptr, m1, NTOK, 4 * CC, 4 * CC, CC);
        tgemm_k<2, true, false, true><<<dim3(CC / 128, NTOK / 64), 256, GEMM_SMEM_BYTES(2)>>>(
            m1, l_fc2w, l_fc2b, x, x, NTOK, CC, CC, 4 * CC);
    }

    layernorm_k<<<NTOK, 256>>>(x, lnf_w, lnf_b, h);
    tgemm_k<4, false, false, false><<<dim3(NPAD / 128, NTOK / 128), 256, GEMM_SMEM_BYTES(4)>>>(
        h, wpad, nullptr, nullptr, out, NTOK, VV, NPAD, CC);
}

// round 8
// speedup vs baseline: 2.6484x; 1.0273x over previous
#include <cuda_runtime.h>
#include <math.h>
#include <stdint.h>

// ---------------- dimensions ----------------
#define BB   2
#define TT   1024
#define CC   768
#define NH   12
#define HD   64
#define LL   4
#define VV   50257
#define NPAD 50304         // 393 * 128, head_w padded columns
#define NTOK 2048          // BB*TT
#define BH   24            // BB*NH

// weight-rounding buffer offsets (floats)
#define WQKV_SZ  ((size_t)LL * CC * 3 * CC)
#define WPROJ_SZ ((size_t)LL * CC * CC)
#define WFC_SZ   ((size_t)LL * CC * 4 * CC)
#define WFC2_SZ  ((size_t)LL * 4 * CC * CC)
#define OFF_QKV  0
#define OFF_PROJ (OFF_QKV + WQKV_SZ)
#define OFF_FC   (OFF_PROJ + WPROJ_SZ)
#define OFF_FC2  (OFF_FC + WFC_SZ)
#define WR_TOTAL (OFF_FC2 + WFC2_SZ)

// ---------------- scratch (static device globals; no allocs) ----------------
__device__ float g_x  [NTOK * CC];
__device__ float g_h  [NTOK * CC];
__device__ float g_qkv[NTOK * 3 * CC];
__device__ float g_y  [NTOK * CC];
__device__ float g_m1 [NTOK * 4 * CC];
__device__ float g_wpad[(size_t)CC * NPAD];   // padded+rounded head weights
__device__ float g_wr [WR_TOTAL];             // tf32-rounded layer weights

// ---------------- helpers ----------------
__device__ __forceinline__ float warpReduceSum(float v) {
    #pragma unroll
    for (int o = 16; o > 0; o >>= 1) v += __shfl_xor_sync(0xffffffffu, v, o);
    return v;
}
__device__ float blockReduceSum(float v) {
    __shared__ float s[32];
    int lane = threadIdx.x & 31, wid = threadIdx.x >> 5;
    v = warpReduceSum(v);
    if (lane == 0) s[wid] = v;
    __syncthreads();
    int nw = blockDim.x >> 5;
    v = (threadIdx.x < nw) ? s[threadIdx.x] : 0.f;
    if (wid == 0) v = warpReduceSum(v);
    if (threadIdx.x == 0) s[0] = v;
    __syncthreads();
    v = s[0];
    __syncthreads();
    return v;
}

__device__ __forceinline__ float gelu_f(float x) {
    const float k = 0.7978845608028654f;  // sqrt(2/pi)
    float x3 = x * x * x;
    return 0.5f * x * (1.f + tanhf(k * (x + 0.044715f * x3)));
}

__device__ __forceinline__ uint32_t f2tf32(float x) {
    uint32_t r;
    asm("cvt.rna.tf32.f32 %0, %1;" : "=r"(r) : "f"(x));
    return r;
}
__device__ __forceinline__ float roundtf(float x) {
    return __uint_as_float(f2tf32(x));
}

__device__ __forceinline__ void mma_tf32(float c[4],
                                         uint32_t a0, uint32_t a1, uint32_t a2, uint32_t a3,
                                         uint32_t b0, uint32_t b1) {
    asm volatile(
        "mma.sync.aligned.m16n8k8.row.col.f32.tf32.tf32.f32 "
        "{%0,%1,%2,%3}, {%4,%5,%6,%7}, {%8,%9}, {%0,%1,%2,%3};\n"
        : "+f"(c[0]), "+f"(c[1]), "+f"(c[2]), "+f"(c[3])
        : "r"(a0), "r"(a1), "r"(a2), "r"(a3), "r"(b0), "r"(b1));
}

// ---------------- cp.async helpers ----------------
__device__ __forceinline__ void cp16(uint32_t dst, const void* src) {
    asm volatile("cp.async.cg.shared.global [%0], [%1], 16;" :: "r"(dst), "l"(src));
}
__device__ __forceinline__ void cp_commit() {
    asm volatile("cp.async.commit_group;");
}
__device__ __forceinline__ void cp_wait1() {
    asm volatile("cp.async.wait_group 1;");
}
__device__ __forceinline__ void cp_wait0() {
    asm volatile("cp.async.wait_group 0;");
}

// ---------------- tf32 rounding copy (weights prep) ----------------
__global__ void round_tf32_k(const float* __restrict__ src, float* __restrict__ dst,
                             size_t n4) {
    size_t i = (size_t)blockIdx.x * blockDim.x + threadIdx.x;
    if (i >= n4) return;
    float4 v = ((const float4*)src)[i];
    v.x = roundtf(v.x); v.y = roundtf(v.y);
    v.z = roundtf(v.z); v.w = roundtf(v.w);
    ((float4*)dst)[i] = v;
}

// ---------------- head weight pad + round: [768][50257] -> [768][50304] ----------------
__global__ void pad_head_k(const float* __restrict__ w, float* __restrict__ wp) {
    size_t idx = (size_t)blockIdx.x * blockDim.x + threadIdx.x;
    size_t base = idx * 4;
    const size_t tot = (size_t)CC * NPAD;
    if (base >= tot) return;
    int r = (int)(base / NPAD);
    int c = (int)(base % NPAD);
    const float* src = w + (size_t)r * VV;
    float4 v;
    v.x = (c + 0 < VV) ? roundtf(src[c + 0]) : 0.f;
    v.y = (c + 1 < VV) ? roundtf(src[c + 1]) : 0.f;
    v.z = (c + 2 < VV) ? roundtf(src[c + 2]) : 0.f;
    v.w = (c + 3 < VV) ? roundtf(src[c + 3]) : 0.f;
    *(float4*)&wp[base] = v;
}

// ---------------- embedding ----------------
__global__ void embed_k(const int* __restrict__ idx, const float* __restrict__ wte,
                        const float* __restrict__ wpe, float* __restrict__ x) {
    int row = blockIdx.x;              // b*TT + t
    int t = row & (TT - 1);
    int tok = idx[row];
    const float* we = wte + (size_t)tok * CC;
    const float* pe = wpe + (size_t)t * CC;
    float* o = x + (size_t)row * CC;
    for (int c = threadIdx.x; c < CC; c += blockDim.x) o[c] = we[c] + pe[c];
}

// ---------------- layernorm (output tf32-rounded: feeds GEMM A-side) ----------------
__global__ void layernorm_k(const float* __restrict__ in, const float* __restrict__ w,
                            const float* __restrict__ b, float* __restrict__ out) {
    int row = blockIdx.x;
    const float* p = in + (size_t)row * CC;
    int tid = threadIdx.x;
    float v[3];
    float s = 0.f;
    #pragma unroll
    for (int i = 0; i < 3; i++) { v[i] = p[tid + i * 256]; s += v[i]; }
    float mean = blockReduceSum(s) * (1.f / (float)CC);
    float vs = 0.f;
    #pragma unroll
    for (int i = 0; i < 3; i++) { float d = v[i] - mean; vs += d * d; }
    float var = blockReduceSum(vs) * (1.f / (float)CC);
    float rstd = rsqrtf(var + 1e-5f);
    float* o = out + (size_t)row * CC;
    #pragma unroll
    for (int i = 0; i < 3; i++) {
        int c = tid + i * 256;
        o[c] = roundtf((v[i] - mean) * rstd * w[c] + b[c]);
    }
}

// ---------------- TF32 tensor-core GEMM (cp.async double-buffered) ----------------
// C[M x Nout] = epi(A[M x K] @ B[K x ldB] restricted to Nout cols).
// Operands MUST already be tf32-rounded in gmem (no cvt in mainloop).
// Block tile (32*MT) x 128, KT=32, 256 threads = 8 warps, warp grid 2(m) x 4(n).
// ldB multiple of 128, grid.x = ldB/128.
// RNDOUT: round the stored result to tf32 (used when output feeds another GEMM).
#define KT   32
#define SA   36
#define SB   132
#define BSZ  (KT * SB)

template <int MT, bool BIAS, bool GELU, bool RESID, bool RNDOUT>
__global__ __launch_bounds__(256, 2) void tgemm_k(
    const float* __restrict__ A, const float* __restrict__ B,
    const float* __restrict__ bias, const float* __restrict__ resid,
    float* __restrict__ C, int M, int Nout, int ldB, int K) {
    extern __shared__ float smem[];

    constexpr int ROWS = 32 * MT;          // A rows per block
    constexpr int ASZ  = ROWS * SA;        // floats
    constexpr int STG  = ASZ + BSZ;        // floats per stage
    constexpr int TPR  = 256 / ROWS;       // threads per A row
    constexpr int KCH  = 32 / TPR;         // k floats per thread
    constexpr int NCPA = KCH / 4;          // cp16 per thread for A

    int tid = threadIdx.x;
    int lane = tid & 31;
    int wid = tid >> 5;
    int warp_m = wid >> 2;             // 0..1
    int warp_n = wid & 3;              // 0..3
    int lr = lane >> 2;                // 0..7
    int lc = lane & 3;                 // 0..3

    int row0 = blockIdx.y * ROWS;
    int col0 = blockIdx.x * 128;

    int aM  = tid / TPR;
    int aK4 = (tid % TPR) * KCH;
    int bK  = tid >> 3;
    int bN4 = (tid & 7) * 4;

    float acc[MT][4][4];
    #pragma unroll
    for (int i = 0; i < MT; i++)
        #pragma unroll
        for (int j = 0; j < 4; j++)
            #pragma unroll
            for (int q = 0; q < 4; q++) acc[i][j][q] = 0.f;

    const float* aSrcBase = A + (size_t)(row0 + aM) * K + aK4;
    const float* bSrcBase = B + (size_t)bK * ldB + col0 + bN4;

    auto load_stage = [&](int kt, int s) {
        float* As = smem + s * STG;
        float* Bs = As + ASZ;
        {
            uint32_t dst = (uint32_t)__cvta_generic_to_shared(&As[aM * SA + aK4]);
            const float* src = aSrcBase + kt;
            #pragma unroll
            for (int u = 0; u < NCPA; u++)
                cp16(dst + u * 16, src + u * 4);
        }
        {
            uint32_t dst = (uint32_t)__cvta_generic_to_shared(&Bs[bK * SB + bN4]);
            const float* src = bSrcBase + (size_t)kt * ldB;
            #pragma unroll
            for (int u = 0; u < 4; u++)
                cp16(dst + u * 32 * 4, src + u * 32);
        }
    };

    int nIter = K / KT;
    load_stage(0, 0);
    cp_commit();

    for (int it = 0; it < nIter; it++) {
        if (it + 1 < nIter) {
            load_stage((it + 1) * KT, (it + 1) & 1);
            cp_commit();
            cp_wait1();
        } else {
            cp_wait0();
        }
        __syncthreads();

        const uint32_t* As = (const uint32_t*)(smem + (it & 1) * STG);
        const uint32_t* Bs = As + ASZ;

        #pragma unroll
        for (int ks = 0; ks < 4; ks++) {
            int k0 = ks * 8;
            uint32_t af[MT][4];
            #pragma unroll
            for (int mt = 0; mt < MT; mt++) {
                int am = warp_m * (MT * 16) + mt * 16;
                af[mt][0] = As[(am + lr    ) * SA + k0 + lc    ];
                af[mt][1] = As[(am + lr + 8) * SA + k0 + lc    ];
                af[mt][2] = As[(am + lr    ) * SA + k0 + lc + 4];
                af[mt][3] = As[(am + lr + 8) * SA + k0 + lc + 4];
            }
            #pragma unroll
            for (int nt = 0; nt < 4; nt++) {
                int bn = warp_n * 32 + nt * 8;
                uint32_t b0 = Bs[(k0 + lc    ) * SB + bn + lr];
                uint32_t b1 = Bs[(k0 + 4 + lc) * SB + bn + lr];
                #pragma unroll
                for (int mt = 0; mt < MT; mt++)
                    mma_tf32(acc[mt][nt], af[mt][0], af[mt][1], af[mt][2], af[mt][3], b0, b1);
            }
        }
        __syncthreads();
    }

    // ---- epilogue ----
    #pragma unroll
    for (int mt = 0; mt < MT; mt++) {
        int rbase = row0 + warp_m * (MT * 16) + mt * 16 + lr;
        #pragma unroll
        for (int nt = 0; nt < 4; nt++) {
            int cbase = col0 + warp_n * 32 + nt * 8 + lc * 2;
            #pragma unroll
            for (int half = 0; half < 2; half++) {
                int r = rbase + half * 8;
                #pragma unroll
                for (int q = 0; q < 2; q++) {
                    int c = cbase + q;
                    if (c < Nout) {
                        float v = acc[mt][nt][half * 2 + q];
                        if (BIAS) v += bias[c];
                        if (GELU) v = gelu_f(v);
                        if (RESID) v += resid[(size_t)r * Nout + c];
                        if (RNDOUT) v = roundtf(v);
                        C[(size_t)r * Nout + c] = v;
                    }
                }
            }
        }
    }
}

#define GEMM_SMEM_BYTES(MT) (2 * ((32 * (MT)) * SA + BSZ) * 4)

// ---------------- fused flash attention (fp32, balanced causal pairing) ----------------
// grid (TT/128, BH), block 256. Each block handles query tiles bx and 15-bx
// sequentially -> every block does exactly 17 s-tile iterations.
// Output y is tf32-rounded (feeds proj GEMM A-side).
__global__ __launch_bounds__(256) void flash_attn_k(const float* __restrict__ qkv,
                                                    float* __restrict__ y) {
    __shared__ float Qt [64][64];   // [d][t]
    __shared__ float KPt[64][64];   // phase 1: K^T [d][s]; phase 2: P^T [s][t]
    __shared__ float Vs [64][64];   // [s][d]

    int bh = blockIdx.y;
    int b = bh / NH, h = bh % NH;
    int tid = threadIdx.x;
    int ty = tid >> 4, tx = tid & 15;
    const int NT = TT / 64;         // 16

    #pragma unroll
    for (int pass = 0; pass < 2; pass++) {
        int qt = (pass == 0) ? (int)blockIdx.x : (NT - 1 - (int)blockIdx.x);
        int t0 = qt * 64;

        // load Q tile transposed (safe: Qt unread during previous pass's PV phase)
        #pragma unroll
        for (int u = 0; u < 4; u++) {
            int idx = tid + u * 256;
            int r = idx >> 4;
            int c4 = (idx & 15) * 4;
            const float* qsrc = qkv + (size_t)(b * TT + t0 + r) * (3 * CC) + h * HD + c4;
            float4 qv = *(const float4*)qsrc;
            Qt[c4 + 0][r] = qv.x;
            Qt[c4 + 1][r] = qv.y;
            Qt[c4 + 2][r] = qv.z;
            Qt[c4 + 3][r] = qv.w;
        }

        float m_i[4], l_i[4], acc[4][4];
        #pragma unroll
        for (int i = 0; i < 4; i++) {
            m_i[i] = -1e30f;
            l_i[i] = 0.f;
            #pragma unroll
            for (int j = 0; j < 4; j++) acc[i][j] = 0.f;
        }

        int nTiles = qt + 1;
        for (int st = 0; st < nTiles; st++) {
            int s0 = st * 64;

            __syncthreads();  // prior phase writes/reads complete before refill
            #pragma unroll
            for (int u = 0; u < 4; u++) {
                int idx = tid + u * 256;
                int r = idx >> 4;
                int c4 = (idx & 15) * 4;
                const float* ksrc = qkv + (size_t)(b * TT + s0 + r) * (3 * CC) + CC + h * HD + c4;
                float4 kv = *(const float4*)ksrc;
                KPt[c4 + 0][r] = kv.x;
                KPt[c4 + 1][r] = kv.y;
                KPt[c4 + 2][r] = kv.z;
                KPt[c4 + 3][r] = kv.w;
                const float* vsrc = qkv + (size_t)(b * TT + s0 + r) * (3 * CC) + 2 * CC + h * HD + c4;
                *(float4*)&Vs[r][c4] = *(const float4*)vsrc;
            }
            __syncthreads();

            float S[4][4];
            #pragma unroll
            for (int i = 0; i < 4; i++)
                #pragma unroll
                for (int j = 0; j < 4; j++) S[i][j] = 0.f;

            #pragma unroll 8
            for (int d = 0; d < 64; d++) {
                float4 aq = *(float4*)&Qt[d][ty * 4];
                float4 bq = *(float4*)&KPt[d][tx * 4];
                float av[4] = {aq.x, aq.y, aq.z, aq.w};
                float bv[4] = {bq.x, bq.y, bq.z, bq.w};
                #pragma unroll
                for (int i = 0; i < 4; i++)
                    #pragma unroll
                    for (int j = 0; j < 4; j++) S[i][j] += av[i] * bv[j];
            }

            __syncthreads();  // all K reads done; KPt becomes P^T below

            const float scale = 0.125f;
            bool diag = (st == qt);
            #pragma unroll
            for (int i = 0; i < 4; i++) {
                int t = t0 + ty * 4 + i;
                #pragma unroll
                for (int j = 0; j < 4; j++) {
                    float v = S[i][j] * scale;
                    if (diag && (s0 + tx * 4 + j > t)) v = -1e30f;
                    S[i][j] = v;
                }
            }

            #pragma unroll
            for (int i = 0; i < 4; i++) {
                float rmax = fmaxf(fmaxf(S[i][0], S[i][1]), fmaxf(S[i][2], S[i][3]));
                #pragma unroll
                for (int o = 8; o > 0; o >>= 1)
                    rmax = fmaxf(rmax, __shfl_xor_sync(0xffffffffu, rmax, o));
                float mnew = fmaxf(m_i[i], rmax);
                float alpha = __expf(m_i[i] - mnew);
                float rsum = 0.f;
                #pragma unroll
                for (int j = 0; j < 4; j++) {
                    float p = __expf(S[i][j] - mnew);
                    S[i][j] = p;
                    rsum += p;
                }
                #pragma unroll
                for (int o = 8; o > 0; o >>= 1)
                    rsum += __shfl_xor_sync(0xffffffffu, rsum, o);
                l_i[i] = l_i[i] * alpha + rsum;
                m_i[i] = mnew;
                #pragma unroll
                for (int j = 0; j < 4; j++) acc[i][j] *= alpha;
            }

            #pragma unroll
            for (int i = 0; i < 4; i++)
                #pragma unroll
                for (int j = 0; j < 4; j++)
                    KPt[tx * 4 + j][ty * 4 + i] = S[i][j];
            __syncthreads();

            #pragma unroll 8
            for (int k = 0; k < 64; k++) {
                float4 ap = *(float4*)&KPt[k][ty * 4];
                float4 vv = *(float4*)&Vs[k][tx * 4];
                float av[4] = {ap.x, ap.y, ap.z, ap.w};
                float bv[4] = {vv.x, vv.y, vv.z, vv.w};
                #pragma unroll
                for (int i = 0; i < 4; i++)
                    #pragma unroll
                    for (int j = 0; j < 4; j++) acc[i][j] += av[i] * bv[j];
            }
        }

        #pragma unroll
        for (int i = 0; i < 4; i++) {
            float inv = 1.f / l_i[i];
            int t = t0 + ty * 4 + i;
            float* orow = y + (size_t)(b * TT + t) * CC + h * HD;
            #pragma unroll
            for (int j = 0; j < 4; j++) orow[tx * 4 + j] = roundtf(acc[i][j] * inv);
        }
        __syncthreads();  // pass isolation (Qt reload vs lingering readers)
    }
}

// ---------------- host launcher ----------------
extern "C" void kernel_launch(void* const* d_in, const int* in_sizes, int n_in,
                              void* d_out, int out_size) {
    (void)in_sizes; (void)n_in; (void)out_size;
    const int*   idx    = (const int*)  d_in[0];
    const float* wte    = (const float*)d_in[1];
    const float* wpe    = (const float*)d_in[2];
    const float* ln1_w  = (const float*)d_in[3];
    const float* ln1_b  = (const float*)d_in[4];
    const float* qkv_w  = (const float*)d_in[5];
    const float* qkv_b  = (const float*)d_in[6];
    const float* proj_w = (const float*)d_in[7];
    const float* proj_b = (const float*)d_in[8];
    const float* ln2_w  = (const float*)d_in[9];
    const float* ln2_b  = (const float*)d_in[10];
    const float* fc_w   = (const float*)d_in[11];
    const float* fc_b   = (const float*)d_in[12];
    const float* fc2_w  = (const float*)d_in[13];
    const float* fc2_b  = (const float*)d_in[14];
    const float* lnf_w  = (const float*)d_in[15];
    const float* lnf_b  = (const float*)d_in[16];
    const float* head_w = (const float*)d_in[17];
    float* out = (float*)d_out;

    float *x, *h, *qkv, *y, *m1, *wpad, *wr;
    cudaGetSymbolAddress((void**)&x,    g_x);
    cudaGetSymbolAddress((void**)&h,    g_h);
    cudaGetSymbolAddress((void**)&qkv,  g_qkv);
    cudaGetSymbolAddress((void**)&y,    g_y);
    cudaGetSymbolAddress((void**)&m1,   g_m1);
    cudaGetSymbolAddress((void**)&wpad, g_wpad);
    cudaGetSymbolAddress((void**)&wr,   g_wr);

    cudaFuncSetAttribute(tgemm_k<4, true,  false, false, false>, cudaFuncAttributeMaxDynamicSharedMemorySize, GEMM_SMEM_BYTES(4));
    cudaFuncSetAttribute(tgemm_k<4, true,  true,  false, true >, cudaFuncAttributeMaxDynamicSharedMemorySize, GEMM_SMEM_BYTES(4));
    cudaFuncSetAttribute(tgemm_k<4, false, false, false, false>, cudaFuncAttributeMaxDynamicSharedMemorySize, GEMM_SMEM_BYTES(4));
    cudaFuncSetAttribute(tgemm_k<2, true,  false, true,  false>, cudaFuncAttributeMaxDynamicSharedMemorySize, GEMM_SMEM_BYTES(2));

    float* wr_qkv  = wr + OFF_QKV;
    float* wr_proj = wr + OFF_PROJ;
    float* wr_fc   = wr + OFF_FC;
    float* wr_fc2  = wr + OFF_FC2;

    // prep: round weights to tf32 once per launch
    round_tf32_k<<<(int)((WQKV_SZ  / 4 + 255) / 256), 256>>>(qkv_w,  wr_qkv,  WQKV_SZ  / 4);
    round_tf32_k<<<(int)((WPROJ_SZ / 4 + 255) / 256), 256>>>(proj_w, wr_proj, WPROJ_SZ / 4);
    round_tf32_k<<<(int)((WFC_SZ   / 4 + 255) / 256), 256>>>(fc_w,   wr_fc,   WFC_SZ   / 4);
    round_tf32_k<<<(int)((WFC2_SZ  / 4 + 255) / 256), 256>>>(fc2_w,  wr_fc2,  WFC2_SZ  / 4);
    {
        size_t tot4 = ((size_t)CC * NPAD) / 4;
        pad_head_k<<<(int)((tot4 + 255) / 256), 256>>>(head_w, wpad);
    }

    embed_k<<<NTOK, 256>>>(idx, wte, wpe, x);

    for (int l = 0; l < LL; l++) {
        const float* l_ln1w  = ln1_w  + (size_t)l * CC;
        const float* l_ln1b  = ln1_b  + (size_t)l * CC;
        const float* l_qkvw  = wr_qkv  + (size_t)l * CC * 3 * CC;
        const float* l_qkvb  = qkv_b  + (size_t)l * 3 * CC;
        const float* l_pw    = wr_proj + (size_t)l * CC * CC;
        const float* l_pb    = proj_b + (size_t)l * CC;
        const float* l_ln2w  = ln2_w  + (size_t)l * CC;
        const float* l_ln2b  = ln2_b  + (size_t)l * CC;
        const float* l_fcw   = wr_fc   + (size_t)l * CC * 4 * CC;
        const float* l_fcb   = fc_b   + (size_t)l * 4 * CC;
        const float* l_fc2w  = wr_fc2  + (size_t)l * 4 * CC * CC;
        const float* l_fc2b  = fc2_b  + (size_t)l * CC;

        layernorm_k<<<NTOK, 256>>>(x, l_ln1w, l_ln1b, h);
        tgemm_k<4, true, false, false, false><<<dim3((3 * CC) / 128, NTOK / 128), 256, GEMM_SMEM_BYTES(4)>>>(
            h, l_qkvw, l_qkvb, nullptr, qkv, NTOK, 3 * CC, 3 * CC, CC);
        flash_attn_k<<<dim3(TT / 128, BH), 256>>>(qkv, y);
        tgemm_k<2, true, false, true, false><<<dim3(CC / 128, NTOK / 64), 256, GEMM_SMEM_BYTES(2)>>>(
            y, l_pw, l_pb, x, x, NTOK, CC, CC, CC);
        layernorm_k<<<NTOK, 256>>>(x, l_ln2w, l_ln2b, h);
        tgemm_k<4, true, true, false, true><<<dim3((4 * CC) / 128, NTOK / 128), 256, GEMM_SMEM_BYTES(4)>>>(
            h, l_fcw, l_fcb, nullptr, m1, NTOK, 4 * CC, 4 * CC, CC);
        tgemm_k<2, true, false, true, false><<<dim3(CC / 128, NTOK / 64), 256, GEMM_SMEM_BYTES(2)>>>(
            m1, l_fc2w, l_fc2b, x, x, NTOK, CC, CC, 4 * CC);
    }

    layernorm_k<<<NTOK, 256>>>(x, lnf_w, lnf_b, h);
    tgemm_k<4, false, false, false, false><<<dim3(NPAD / 128, NTOK / 128), 256, GEMM_SMEM_BYTES(4)>>>(
        h, wpad, nullptr, nullptr, out, NTOK, VV, NPAD, CC);
}